// round 11
// baseline (speedup 1.0000x reference)
#include <cuda_runtime.h>
#include <cuda_fp16.h>
#include <cstdint>

#define V_N 20000
#define V_PAD 20032      // 313 * 64
#define E_N 40000
#define E_PAD 40064      // 313 * 128
#define NT 313           // 128-row M tiles in ew gemm
#define NIN 74
#define EIN 12
#define D 64
#define EH 128
#define DD 4096
#define STEPS 6

// ---------------- scratch (static device globals; zero-initialized) ---------
__device__ float  d_h[V_PAD * D];
__device__ float  d_neigh[V_PAD * D];
__device__ __half d_z[E_PAD * EH];
__device__ __half d_ew[(size_t)E_PAD * DD];
__device__ __half d_Wg[256 * EH];              // packed GRU weights (fp16)

// ---------------- asm helpers -------------------------------------------------
__device__ __forceinline__ uint32_t smem_u32(const void* p) {
    uint32_t a;
    asm("{ .reg .u64 t; cvta.to.shared.u64 t, %1; cvt.u32.u64 %0, t; }" : "=r"(a) : "l"(p));
    return a;
}
__device__ __forceinline__ void cp16(uint32_t s, const void* g) {
    asm volatile("cp.async.cg.shared.global [%0], [%1], 16;" :: "r"(s), "l"(g));
}
#define CP_COMMIT() asm volatile("cp.async.commit_group;" ::: "memory")
#define CP_WAIT0()  asm volatile("cp.async.wait_group 0;" ::: "memory")

__device__ __forceinline__ void ldsm_x4(uint32_t addr, uint32_t& r0, uint32_t& r1,
                                        uint32_t& r2, uint32_t& r3) {
    asm volatile("ldmatrix.sync.aligned.m8n8.x4.shared.b16 {%0,%1,%2,%3}, [%4];"
                 : "=r"(r0), "=r"(r1), "=r"(r2), "=r"(r3) : "r"(addr));
}
__device__ __forceinline__ void ldsm_x2(uint32_t addr, uint32_t& r0, uint32_t& r1) {
    asm volatile("ldmatrix.sync.aligned.m8n8.x2.shared.b16 {%0,%1}, [%2];"
                 : "=r"(r0), "=r"(r1) : "r"(addr));
}
__device__ __forceinline__ void mma16816(float* c, const uint32_t* a, const uint32_t* b) {
    asm volatile("mma.sync.aligned.m16n8k16.row.col.f32.f16.f16.f32 "
                 "{%0,%1,%2,%3}, {%4,%5,%6,%7}, {%8,%9}, {%0,%1,%2,%3};"
                 : "+f"(c[0]), "+f"(c[1]), "+f"(c[2]), "+f"(c[3])
                 : "r"(a[0]), "r"(a[1]), "r"(a[2]), "r"(a[3]), "r"(b[0]), "r"(b[1]));
}

// ---------------- fused prep: zhid (2500 blk) + proj (1250 blk) + wg (128 blk)
#define ZB 2500
#define PB 1250
#define WB 128
__global__ void prep_all(const float* __restrict__ ef,  const float* __restrict__ W1,
                         const float* __restrict__ b1,  const float* __restrict__ nf,
                         const float* __restrict__ pW,  const float* __restrict__ pb,
                         const float* __restrict__ Wih, const float* __restrict__ Whh) {
    __shared__ char sb[24320];
    const int tid = threadIdx.x;
    const int bx  = blockIdx.x;

    if (bx < ZB) {
        float* W1s = (float*)sb;
        float* b1s = (float*)(sb + 6144);
        float* efs = (float*)(sb + 6656);
        const int e0 = bx * 16;
        for (int idx = tid; idx < EH * EIN; idx += 256) {
            int k = idx / EIN, i = idx % EIN;
            W1s[i * EH + k] = W1[idx];
        }
        for (int idx = tid; idx < 16 * EIN; idx += 256) {
            int e = idx / EIN, i = idx % EIN;
            efs[e * EIN + i] = ef[(size_t)(e0 + e) * EIN + i];
        }
        if (tid < EH) b1s[tid] = b1[tid];
        __syncthreads();
        const int k = tid & 127, g = tid >> 7;
        #pragma unroll
        for (int ee = 0; ee < 8; ee++) {
            int e = g * 8 + ee;
            float acc = b1s[k];
            #pragma unroll
            for (int i = 0; i < EIN; i++)
                acc = fmaf(W1s[i * EH + k], efs[e * EIN + i], acc);
            d_z[(size_t)(e0 + e) * EH + k] = __float2half(fmaxf(acc, 0.f));
        }
    } else if (bx < ZB + PB) {
        float* Ws  = (float*)sb;
        float* nfs = (float*)(sb + 18944);
        float* bs  = (float*)(sb + 23808);
        const int v0 = (bx - ZB) * 16;
        for (int idx = tid; idx < D * NIN; idx += 256) {
            int o = idx / NIN, i = idx % NIN;
            Ws[i * D + o] = pW[idx];
        }
        for (int idx = tid; idx < 16 * NIN; idx += 256) {
            int n = idx / NIN, i = idx % NIN;
            nfs[n * (NIN + 2) + i] = nf[(size_t)(v0 + n) * NIN + i];
        }
        if (tid < D) bs[tid] = pb[tid];
        __syncthreads();
        const int o = tid & 63, g = tid >> 6;
        #pragma unroll
        for (int nn = 0; nn < 4; nn++) {
            int n = g * 4 + nn;
            float acc = bs[o];
            #pragma unroll
            for (int i = 0; i < NIN; i++)
                acc = fmaf(Ws[i * D + o], nfs[n * (NIN + 2) + i], acc);
            d_h[(size_t)(v0 + n) * D + o] = fmaxf(acc, 0.f);
            d_neigh[(size_t)(v0 + n) * D + o] = 0.f;
        }
    } else {
        int idx = (bx - ZB - PB) * 256 + tid;
        if (idx < 256 * EH) {
            int r = idx >> 7, k = idx & 127;
            float v = 0.f;
            if (r < 128) {
                v = (k < 64) ? Wih[r * D + k] : Whh[r * D + (k - 64)];
            } else if (r < 192) {
                if (k < 64) v = Wih[r * D + k];
            } else {
                if (k >= 64) v = Whh[(r - 64) * D + (k - 64)];
            }
            d_Wg[idx] = __float2half(v);
        }
    }
}

// ---------------- ew GEMM (R8 version: PTX mma, direct half2 epilogue) --------
#define ASTR 152
#define BSTR 152
#define B_BYTES   (128 * BSTR * 2)
#define A_BYTES   (128 * ASTR * 2)
#define A_OFF     B_BYTES
#define EW_SMEM   (A_OFF + A_BYTES)            // 77824 -> 2 CTAs/SM
#define NSLABS 32
#define MGROUPS 9

__global__ __launch_bounds__(256, 2) void ew_gemm(const float* __restrict__ W2,
                                                  const float* __restrict__ b2) {
    extern __shared__ char smem[];
    __half* Bs = (__half*)smem;
    __half* As = (__half*)(smem + A_OFF);
    const uint32_t sbase = smem_u32(smem);
    const int tid  = threadIdx.x;
    const int lane = tid & 31;
    const int w    = tid >> 5;
    const int wm   = w & 3;
    const int wn   = w >> 2;
    const int n0   = blockIdx.x * 128;
    const int by   = blockIdx.y;

    for (int q = tid; q < 4096; q += 256) {
        int n = q >> 5, k4 = (q & 31) * 4;
        float4 v = *(const float4*)&W2[(size_t)(n0 + n) * EH + k4];
        __half t4[4] = { __float2half(v.x), __float2half(v.y),
                         __float2half(v.z), __float2half(v.w) };
        *(uint2*)&Bs[n * BSTR + k4] = *(uint2*)t4;
    }
    for (int q = tid; q < 2048; q += 256) {
        int n = q >> 4, k = 128 + (q & 15);
        Bs[n * BSTR + k] = (k == 128) ? __float2half(b2[n0 + n]) : __half(0);
    }
    for (int q = tid; q < 2048; q += 256) {
        int r = q >> 4, k = 128 + (q & 15);
        As[r * ASTR + k] = (k == 128) ? __float2half(1.f) : __half(0);
    }
    for (int q = tid; q < 2048; q += 256) {
        int r = q >> 4, c = (q & 15) * 8;
        cp16(sbase + A_OFF + (uint32_t)(r * ASTR + c) * 2,
             &d_z[(size_t)(by * 128 + r) * EH + c]);
    }
    CP_COMMIT();

    const int a_r = lane & 15, a_c = (lane >> 4) * 8;
    const int b_r = lane & 7,  b_c = ((lane >> 3) & 1) * 8;
    const uint32_t aAddr0 = sbase + A_OFF + (uint32_t)((wm * 32 + a_r) * ASTR + a_c) * 2;
    const uint32_t bAddr0 = sbase + (uint32_t)((wn * 64 + b_r) * BSTR + b_c) * 2;

    const int TPT = (NT + MGROUPS - 1) / MGROUPS;
    for (int mt = 0; mt < TPT; mt++) {
        int t = by + MGROUPS * mt;
        if (t >= NT) break;
        CP_WAIT0();
        __syncthreads();

        float c[2][8][4];
        #pragma unroll
        for (int i = 0; i < 2; i++)
            #pragma unroll
            for (int j = 0; j < 8; j++)
                #pragma unroll
                for (int q = 0; q < 4; q++) c[i][j][q] = 0.f;

        #pragma unroll
        for (int kc = 0; kc < 9; kc++) {
            uint32_t a[2][4];
            #pragma unroll
            for (int i = 0; i < 2; i++)
                ldsm_x4(aAddr0 + (uint32_t)(i * 16 * ASTR + kc * 16) * 2,
                        a[i][0], a[i][1], a[i][2], a[i][3]);
            uint32_t b[8][2];
            #pragma unroll
            for (int j = 0; j < 8; j++)
                ldsm_x2(bAddr0 + (uint32_t)(j * 8 * BSTR + kc * 16) * 2,
                        b[j][0], b[j][1]);
            #pragma unroll
            for (int i = 0; i < 2; i++)
                #pragma unroll
                for (int j = 0; j < 8; j++)
                    mma16816(c[i][j], a[i], b[j]);
        }
        __syncthreads();

        int tn = t + MGROUPS;
        if (tn < NT) {
            for (int q = tid; q < 2048; q += 256) {
                int r = q >> 4, cc = (q & 15) * 8;
                cp16(sbase + A_OFF + (uint32_t)(r * ASTR + cc) * 2,
                     &d_z[(size_t)(tn * 128 + r) * EH + cc]);
            }
            CP_COMMIT();
        }

        const int rbase = t * 128 + wm * 32 + (lane >> 2);
        const int cbase = n0 + wn * 64 + 2 * (lane & 3);
        #pragma unroll
        for (int i = 0; i < 2; i++) {
            size_t rowo = (size_t)(rbase + i * 16) * DD;
            #pragma unroll
            for (int j = 0; j < 8; j++) {
                int col = cbase + j * 8;
                *(__half2*)&d_ew[rowo + col] =
                    __floats2half2_rn(c[i][j][0], c[i][j][1]);
                *(__half2*)&d_ew[rowo + 8 * DD + col] =
                    __floats2half2_rn(c[i][j][2], c[i][j][3]);
            }
        }
    }
}

// ---------------- per-step kernels -------------------------------------------
// warp per edge, LDG.128 rows (at HBM/LTS ceiling per R9 ncu)
__global__ void scatter_kernel(const int* __restrict__ src, const int* __restrict__ dst) {
    int wg   = (blockIdx.x * blockDim.x + threadIdx.x) >> 5;
    int lane = threadIdx.x & 31;
    if (wg >= E_N) return;
    int se = __ldg(&src[wg]), de = __ldg(&dst[wg]);
    float2 hv = ((const float2*)(d_h + (size_t)se * D))[lane];
    const int4* W4 = (const int4*)(d_ew + (size_t)wg * DD);
    const int rsub = lane >> 3;
    const int cg   = lane & 7;
    float acc[8] = {0.f, 0.f, 0.f, 0.f, 0.f, 0.f, 0.f, 0.f};

    #pragma unroll
    for (int i = 0; i < 16; i++) {
        int r = 4 * i + rsub;
        int4 wv = __ldg(&W4[r * 8 + cg]);
        float hx = __shfl_sync(0xffffffffu, hv.x, 2 * i + (lane >> 4));
        float hy = __shfl_sync(0xffffffffu, hv.y, 2 * i + (lane >> 4));
        float hr = (rsub & 1) ? hy : hx;
        const __half2* wh = (const __half2*)&wv;
        #pragma unroll
        for (int q = 0; q < 4; q++) {
            float2 f = __half22float2(wh[q]);
            acc[2 * q]     = fmaf(hr, f.x, acc[2 * q]);
            acc[2 * q + 1] = fmaf(hr, f.y, acc[2 * q + 1]);
        }
    }
    #pragma unroll
    for (int j = 0; j < 8; j++) {
        acc[j] += __shfl_xor_sync(0xffffffffu, acc[j], 8);
        acc[j] += __shfl_xor_sync(0xffffffffu, acc[j], 16);
    }
    if (lane < 8) {
        float* nb = d_neigh + (size_t)de * D + lane * 8;
        #pragma unroll
        for (int j = 0; j < 8; j++) atomicAdd(nb + j, acc[j]);
    }
}

// GRU v2: latency-optimized. M=32 nodes/block, B frags LDG'd straight from
// d_Wg (L1/L2-resident), small static smem (Xs 8.7KB + Cs 33.8KB) -> 4 CTAs/SM.
#define GXSTR 136
#define GCSTR 264
__global__ __launch_bounds__(256, 4) void gru_mm(const float* __restrict__ conv_b,
                                                 const float* __restrict__ bih,
                                                 const float* __restrict__ bhh) {
    __shared__ __half Xs[32 * GXSTR];
    __shared__ float  Cs[32 * GCSTR];
    const int tid  = threadIdx.x;
    const int lane = tid & 31;
    const int w    = tid >> 5;
    const int wm   = w & 1;        // 2 M groups of 16 nodes
    const int wn   = w >> 1;       // 4 N groups of 64 gate cols
    const int v0   = blockIdx.x * 32;

    // stage X = [relu(neigh+cb) | h] fp16
    for (int q = tid; q < 2048; q += 256) {
        int r = q >> 6, k = q & 63;
        float xv = fmaxf(d_neigh[(size_t)(v0 + r) * D + k] + __ldg(&conv_b[k]), 0.f);
        Xs[r * GXSTR + k]      = __float2half(xv);
        Xs[r * GXSTR + 64 + k] = __float2half(d_h[(size_t)(v0 + r) * D + k]);
    }
    __syncthreads();

    const uint32_t xbase = smem_u32(Xs);
    const int a_r = lane & 15, a_c = (lane >> 4) * 8;
    const uint32_t aAddr0 = xbase + (uint32_t)((wm * 16 + a_r) * GXSTR + a_c) * 2;
    // B fragment gmem base: row n = wn*64 + j*8 + lane/4 ; k = kc*16 + 2*(lane&3)
    const __half* wbase = d_Wg + (size_t)(wn * 64 + (lane >> 2)) * EH + 2 * (lane & 3);

    float c[8][4];
    #pragma unroll
    for (int j = 0; j < 8; j++)
        #pragma unroll
        for (int q = 0; q < 4; q++) c[j][q] = 0.f;

    #pragma unroll
    for (int kc = 0; kc < 8; kc++) {
        uint32_t a[4];
        ldsm_x4(aAddr0 + kc * 32, a[0], a[1], a[2], a[3]);
        #pragma unroll
        for (int j = 0; j < 8; j++) {
            const __half* wp = wbase + j * 8 * EH + kc * 16;
            uint32_t b[2];
            b[0] = *(const uint32_t*)wp;
            b[1] = *(const uint32_t*)(wp + 8);
            mma16816(c[j], a, b);
        }
    }

    // stage C (fp32) by direct fragment mapping
    {
        int crow = wm * 16 + (lane >> 2);
        int cc0  = wn * 64 + 2 * (lane & 3);
        #pragma unroll
        for (int j = 0; j < 8; j++) {
            int cc = cc0 + j * 8;
            *(float2*)&Cs[crow * GCSTR + cc]       = make_float2(c[j][0], c[j][1]);
            *(float2*)&Cs[(crow + 8) * GCSTR + cc] = make_float2(c[j][2], c[j][3]);
        }
    }
    __syncthreads();

    // fused gates + h update + neigh re-zero
    for (int q = tid; q < 2048; q += 256) {
        int r = q >> 6, j = q & 63;
        int v = v0 + r;
        if (v >= V_N) continue;
        const float* cr = Cs + r * GCSTR;
        float g0 = cr[j], g1 = cr[64 + j], g2 = cr[128 + j], g3 = cr[192 + j];
        float rg = 1.f / (1.f + __expf(-(g0 + __ldg(&bih[j])      + __ldg(&bhh[j]))));
        float zg = 1.f / (1.f + __expf(-(g1 + __ldg(&bih[64 + j]) + __ldg(&bhh[64 + j]))));
        float nx = g2 + __ldg(&bih[128 + j]) + rg * (g3 + __ldg(&bhh[128 + j]));
        float e2 = __expf(2.f * nx);
        float ng = 1.f - 2.f / (e2 + 1.f);     // tanh, saturates safely
        size_t gi = (size_t)v * D + j;
        float hp = d_h[gi];
        d_h[gi] = (1.f - zg) * ng + zg * hp;
        d_neigh[gi] = 0.f;
    }
}

__global__ void pred_kernel(const int* __restrict__ src, const int* __restrict__ dst,
                            const float* __restrict__ pW, const float* __restrict__ pb,
                            float* __restrict__ out) {
    int wg   = (blockIdx.x * blockDim.x + threadIdx.x) >> 5;
    int lane = threadIdx.x & 31;
    if (wg >= E_N) return;
    int se = src[wg], de = dst[wg];
    float2 a  = ((const float2*)(d_h + (size_t)se * D))[lane];
    float2 b  = ((const float2*)(d_h + (size_t)de * D))[lane];
    float2 w1 = ((const float2*)pW)[lane];
    float2 w2 = ((const float2*)pW)[32 + lane];
    float acc = a.x * w1.x + a.y * w1.y + b.x * w2.x + b.y * w2.y;
    #pragma unroll
    for (int off = 16; off > 0; off >>= 1)
        acc += __shfl_down_sync(0xffffffffu, acc, off);
    if (lane == 0) out[wg] = acc + pb[0];
}

// ---------------- launch ------------------------------------------------------
extern "C" void kernel_launch(void* const* d_in, const int* in_sizes, int n_in,
                              void* d_out, int out_size) {
    const float* node_feats = (const float*)d_in[0];
    const float* edge_feats = (const float*)d_in[1];
    const int*   src        = (const int*)d_in[2];
    const int*   dst        = (const int*)d_in[3];
    const float* proj_W     = (const float*)d_in[4];
    const float* proj_b     = (const float*)d_in[5];
    const float* en_W1      = (const float*)d_in[6];
    const float* en_b1      = (const float*)d_in[7];
    const float* en_W2      = (const float*)d_in[8];
    const float* en_b2      = (const float*)d_in[9];
    const float* conv_b     = (const float*)d_in[10];
    const float* gru_Wih    = (const float*)d_in[11];
    const float* gru_Whh    = (const float*)d_in[12];
    const float* gru_bih    = (const float*)d_in[13];
    const float* gru_bhh    = (const float*)d_in[14];
    const float* pred_W     = (const float*)d_in[15];
    const float* pred_b     = (const float*)d_in[16];
    float* out = (float*)d_out;

    static int attr_set = 0;
    if (!attr_set) {
        cudaFuncSetAttribute(ew_gemm, cudaFuncAttributeMaxDynamicSharedMemorySize, EW_SMEM);
        attr_set = 1;
    }

    prep_all<<<ZB + PB + WB, 256>>>(edge_feats, en_W1, en_b1, node_feats,
                                    proj_W, proj_b, gru_Wih, gru_Whh);   // 1
    dim3 gg(NSLABS, MGROUPS);                                            // (32, 9)
    ew_gemm<<<gg, 256, EW_SMEM>>>(en_W2, en_b2);                         // 2

    for (int s = 0; s < STEPS; s++) {
        scatter_kernel<<<E_N / 8, 256>>>(src, dst);                      // 3 on s=0
        gru_mm<<<V_PAD / 32, 256>>>(conv_b, gru_bih, gru_bhh);           // 4 on s=0 (profiled)
    }
    pred_kernel<<<E_N / 8, 256>>>(src, dst, pred_W, pred_b, out);
}

// round 12
// speedup vs baseline: 1.2070x; 1.2070x over previous
#include <cuda_runtime.h>
#include <cuda_fp16.h>
#include <cstdint>

#define V_N 20000
#define V_PAD 20032      // 313 * 64
#define E_N 40000
#define E_PAD 40064      // 313 * 128
#define NT 313           // 128-row M tiles in ew gemm
#define NIN 74
#define EIN 12
#define D 64
#define EH 128
#define DD 4096
#define STEPS 6

// ---------------- scratch (static device globals; zero-initialized) ---------
__device__ float    d_h[V_PAD * D];
__device__ float    d_neigh[V_PAD * D];
__device__ __half   d_z[E_PAD * EH];
__device__ __half   d_ew[(size_t)E_PAD * DD];
__device__ uint32_t d_WgF[4 * 8 * 8 * 64];     // fragment-ordered GRU weights (64KB)

// ---------------- asm helpers -------------------------------------------------
__device__ __forceinline__ uint32_t smem_u32(const void* p) {
    uint32_t a;
    asm("{ .reg .u64 t; cvta.to.shared.u64 t, %1; cvt.u32.u64 %0, t; }" : "=r"(a) : "l"(p));
    return a;
}
__device__ __forceinline__ void cp16(uint32_t s, const void* g) {
    asm volatile("cp.async.cg.shared.global [%0], [%1], 16;" :: "r"(s), "l"(g));
}
#define CP_COMMIT() asm volatile("cp.async.commit_group;" ::: "memory")
#define CP_WAIT0()  asm volatile("cp.async.wait_group 0;" ::: "memory")

__device__ __forceinline__ void ldsm_x4(uint32_t addr, uint32_t& r0, uint32_t& r1,
                                        uint32_t& r2, uint32_t& r3) {
    asm volatile("ldmatrix.sync.aligned.m8n8.x4.shared.b16 {%0,%1,%2,%3}, [%4];"
                 : "=r"(r0), "=r"(r1), "=r"(r2), "=r"(r3) : "r"(addr));
}
__device__ __forceinline__ void ldsm_x2(uint32_t addr, uint32_t& r0, uint32_t& r1) {
    asm volatile("ldmatrix.sync.aligned.m8n8.x2.shared.b16 {%0,%1}, [%2];"
                 : "=r"(r0), "=r"(r1) : "r"(addr));
}
__device__ __forceinline__ void mma16816(float* c, const uint32_t* a, const uint32_t* b) {
    asm volatile("mma.sync.aligned.m16n8k16.row.col.f32.f16.f16.f32 "
                 "{%0,%1,%2,%3}, {%4,%5,%6,%7}, {%8,%9}, {%0,%1,%2,%3};"
                 : "+f"(c[0]), "+f"(c[1]), "+f"(c[2]), "+f"(c[3])
                 : "r"(a[0]), "r"(a[1]), "r"(a[2]), "r"(a[3]), "r"(b[0]), "r"(b[1]));
}

// packed GRU weight value: Wg[256][128]; rows 0:64 [Wih_r|Whh_r],
// 64:128 [Wih_z|Whh_z], 128:192 [Wih_n|0], 192:256 [0|Whh_n]
__device__ __forceinline__ float wg_val(int r, int k,
                                        const float* __restrict__ Wih,
                                        const float* __restrict__ Whh) {
    if (r < 128)  return (k < 64) ? Wih[r * D + k] : Whh[r * D + (k - 64)];
    if (r < 192)  return (k < 64) ? Wih[r * D + k] : 0.f;
    return (k >= 64) ? Whh[(r - 64) * D + (k - 64)] : 0.f;
}

// ---------------- fused prep: zhid (2500 blk) + proj (1250 blk) + wg (32 blk)
#define ZB 2500
#define PB 1250
#define WB 32
__global__ void prep_all(const float* __restrict__ ef,  const float* __restrict__ W1,
                         const float* __restrict__ b1,  const float* __restrict__ nf,
                         const float* __restrict__ pW,  const float* __restrict__ pb,
                         const float* __restrict__ Wih, const float* __restrict__ Whh) {
    __shared__ char sb[24320];
    const int tid = threadIdx.x;
    const int bx  = blockIdx.x;

    if (bx < ZB) {
        float* W1s = (float*)sb;
        float* b1s = (float*)(sb + 6144);
        float* efs = (float*)(sb + 6656);
        const int e0 = bx * 16;
        for (int idx = tid; idx < EH * EIN; idx += 256) {
            int k = idx / EIN, i = idx % EIN;
            W1s[i * EH + k] = W1[idx];
        }
        for (int idx = tid; idx < 16 * EIN; idx += 256) {
            int e = idx / EIN, i = idx % EIN;
            efs[e * EIN + i] = ef[(size_t)(e0 + e) * EIN + i];
        }
        if (tid < EH) b1s[tid] = b1[tid];
        __syncthreads();
        const int k = tid & 127, g = tid >> 7;
        #pragma unroll
        for (int ee = 0; ee < 8; ee++) {
            int e = g * 8 + ee;
            float acc = b1s[k];
            #pragma unroll
            for (int i = 0; i < EIN; i++)
                acc = fmaf(W1s[i * EH + k], efs[e * EIN + i], acc);
            d_z[(size_t)(e0 + e) * EH + k] = __float2half(fmaxf(acc, 0.f));
        }
    } else if (bx < ZB + PB) {
        float* Ws  = (float*)sb;
        float* nfs = (float*)(sb + 18944);
        float* bs  = (float*)(sb + 23808);
        const int v0 = (bx - ZB) * 16;
        for (int idx = tid; idx < D * NIN; idx += 256) {
            int o = idx / NIN, i = idx % NIN;
            Ws[i * D + o] = pW[idx];
        }
        for (int idx = tid; idx < 16 * NIN; idx += 256) {
            int n = idx / NIN, i = idx % NIN;
            nfs[n * (NIN + 2) + i] = nf[(size_t)(v0 + n) * NIN + i];
        }
        if (tid < D) bs[tid] = pb[tid];
        __syncthreads();
        const int o = tid & 63, g = tid >> 6;
        #pragma unroll
        for (int nn = 0; nn < 4; nn++) {
            int n = g * 4 + nn;
            float acc = bs[o];
            #pragma unroll
            for (int i = 0; i < NIN; i++)
                acc = fmaf(Ws[i * D + o], nfs[n * (NIN + 2) + i], acc);
            d_h[(size_t)(v0 + n) * D + o] = fmaxf(acc, 0.f);
            d_neigh[(size_t)(v0 + n) * D + o] = 0.f;
        }
    } else {
        // fragment-ordered Wg: t indexes (wn, j, kc, lane); two packed words
        int t = (bx - ZB - PB) * 256 + tid;      // 0..8191
        int lane = t & 31, kc = (t >> 5) & 7, j = (t >> 8) & 7, wn = t >> 11;
        int n  = wn * 64 + j * 8 + (lane >> 2);
        int k0 = kc * 16 + 2 * (lane & 3);
        __half2 w0 = __floats2half2_rn(wg_val(n, k0,     Wih, Whh),
                                       wg_val(n, k0 + 1, Wih, Whh));
        __half2 w1 = __floats2half2_rn(wg_val(n, k0 + 8, Wih, Whh),
                                       wg_val(n, k0 + 9, Wih, Whh));
        d_WgF[t * 2]     = *(uint32_t*)&w0;
        d_WgF[t * 2 + 1] = *(uint32_t*)&w1;
    }
}

// ---------------- ew GEMM (best measured: PTX mma, direct half2 epilogue) -----
#define ASTR 152
#define BSTR 152
#define B_BYTES   (128 * BSTR * 2)
#define A_BYTES   (128 * ASTR * 2)
#define A_OFF     B_BYTES
#define EW_SMEM   (A_OFF + A_BYTES)            // 77824 -> 2 CTAs/SM
#define NSLABS 32
#define MGROUPS 9

__global__ __launch_bounds__(256, 2) void ew_gemm(const float* __restrict__ W2,
                                                  const float* __restrict__ b2) {
    extern __shared__ char smem[];
    __half* Bs = (__half*)smem;
    __half* As = (__half*)(smem + A_OFF);
    const uint32_t sbase = smem_u32(smem);
    const int tid  = threadIdx.x;
    const int lane = tid & 31;
    const int w    = tid >> 5;
    const int wm   = w & 3;
    const int wn   = w >> 2;
    const int n0   = blockIdx.x * 128;
    const int by   = blockIdx.y;

    for (int q = tid; q < 4096; q += 256) {
        int n = q >> 5, k4 = (q & 31) * 4;
        float4 v = *(const float4*)&W2[(size_t)(n0 + n) * EH + k4];
        __half t4[4] = { __float2half(v.x), __float2half(v.y),
                         __float2half(v.z), __float2half(v.w) };
        *(uint2*)&Bs[n * BSTR + k4] = *(uint2*)t4;
    }
    for (int q = tid; q < 2048; q += 256) {
        int n = q >> 4, k = 128 + (q & 15);
        Bs[n * BSTR + k] = (k == 128) ? __float2half(b2[n0 + n]) : __half(0);
    }
    for (int q = tid; q < 2048; q += 256) {
        int r = q >> 4, k = 128 + (q & 15);
        As[r * ASTR + k] = (k == 128) ? __float2half(1.f) : __half(0);
    }
    for (int q = tid; q < 2048; q += 256) {
        int r = q >> 4, c = (q & 15) * 8;
        cp16(sbase + A_OFF + (uint32_t)(r * ASTR + c) * 2,
             &d_z[(size_t)(by * 128 + r) * EH + c]);
    }
    CP_COMMIT();

    const int a_r = lane & 15, a_c = (lane >> 4) * 8;
    const int b_r = lane & 7,  b_c = ((lane >> 3) & 1) * 8;
    const uint32_t aAddr0 = sbase + A_OFF + (uint32_t)((wm * 32 + a_r) * ASTR + a_c) * 2;
    const uint32_t bAddr0 = sbase + (uint32_t)((wn * 64 + b_r) * BSTR + b_c) * 2;

    const int TPT = (NT + MGROUPS - 1) / MGROUPS;
    for (int mt = 0; mt < TPT; mt++) {
        int t = by + MGROUPS * mt;
        if (t >= NT) break;
        CP_WAIT0();
        __syncthreads();

        float c[2][8][4];
        #pragma unroll
        for (int i = 0; i < 2; i++)
            #pragma unroll
            for (int j = 0; j < 8; j++)
                #pragma unroll
                for (int q = 0; q < 4; q++) c[i][j][q] = 0.f;

        #pragma unroll
        for (int kc = 0; kc < 9; kc++) {
            uint32_t a[2][4];
            #pragma unroll
            for (int i = 0; i < 2; i++)
                ldsm_x4(aAddr0 + (uint32_t)(i * 16 * ASTR + kc * 16) * 2,
                        a[i][0], a[i][1], a[i][2], a[i][3]);
            uint32_t b[8][2];
            #pragma unroll
            for (int j = 0; j < 8; j++)
                ldsm_x2(bAddr0 + (uint32_t)(j * 8 * BSTR + kc * 16) * 2,
                        b[j][0], b[j][1]);
            #pragma unroll
            for (int i = 0; i < 2; i++)
                #pragma unroll
                for (int j = 0; j < 8; j++)
                    mma16816(c[i][j], a[i], b[j]);
        }
        __syncthreads();

        int tn = t + MGROUPS;
        if (tn < NT) {
            for (int q = tid; q < 2048; q += 256) {
                int r = q >> 4, cc = (q & 15) * 8;
                cp16(sbase + A_OFF + (uint32_t)(r * ASTR + cc) * 2,
                     &d_z[(size_t)(tn * 128 + r) * EH + cc]);
            }
            CP_COMMIT();
        }

        const int rbase = t * 128 + wm * 32 + (lane >> 2);
        const int cbase = n0 + wn * 64 + 2 * (lane & 3);
        #pragma unroll
        for (int i = 0; i < 2; i++) {
            size_t rowo = (size_t)(rbase + i * 16) * DD;
            #pragma unroll
            for (int j = 0; j < 8; j++) {
                int col = cbase + j * 8;
                *(__half2*)&d_ew[rowo + col] =
                    __floats2half2_rn(c[i][j][0], c[i][j][1]);
                *(__half2*)&d_ew[rowo + 8 * DD + col] =
                    __floats2half2_rn(c[i][j][2], c[i][j][3]);
            }
        }
    }
}

// ---------------- per-step kernels -------------------------------------------
// warp per edge, LDG.128 rows (at HBM/LTS ceiling per R9 ncu)
__global__ void scatter_kernel(const int* __restrict__ src, const int* __restrict__ dst) {
    int wg   = (blockIdx.x * blockDim.x + threadIdx.x) >> 5;
    int lane = threadIdx.x & 31;
    if (wg >= E_N) return;
    int se = __ldg(&src[wg]), de = __ldg(&dst[wg]);
    float2 hv = ((const float2*)(d_h + (size_t)se * D))[lane];
    const int4* W4 = (const int4*)(d_ew + (size_t)wg * DD);
    const int rsub = lane >> 3;
    const int cg   = lane & 7;
    float acc[8] = {0.f, 0.f, 0.f, 0.f, 0.f, 0.f, 0.f, 0.f};

    #pragma unroll
    for (int i = 0; i < 16; i++) {
        int r = 4 * i + rsub;
        int4 wv = __ldg(&W4[r * 8 + cg]);
        float hx = __shfl_sync(0xffffffffu, hv.x, 2 * i + (lane >> 4));
        float hy = __shfl_sync(0xffffffffu, hv.y, 2 * i + (lane >> 4));
        float hr = (rsub & 1) ? hy : hx;
        const __half2* wh = (const __half2*)&wv;
        #pragma unroll
        for (int q = 0; q < 4; q++) {
            float2 f = __half22float2(wh[q]);
            acc[2 * q]     = fmaf(hr, f.x, acc[2 * q]);
            acc[2 * q + 1] = fmaf(hr, f.y, acc[2 * q + 1]);
        }
    }
    #pragma unroll
    for (int j = 0; j < 8; j++) {
        acc[j] += __shfl_xor_sync(0xffffffffu, acc[j], 8);
        acc[j] += __shfl_xor_sync(0xffffffffu, acc[j], 16);
    }
    if (lane < 8) {
        float* nb = d_neigh + (size_t)de * D + lane * 8;
        #pragma unroll
        for (int j = 0; j < 8; j++) atomicAdd(nb + j, acc[j]);
    }
}

// GRU v3: M=32 nodes/block, B frags via fragment-ordered d_WgF (coalesced
// LDG.64), float4 staging, 4 CTAs/SM.
#define GXSTR 136
#define GCSTR 264
__global__ __launch_bounds__(256, 4) void gru_mm(const float* __restrict__ conv_b,
                                                 const float* __restrict__ bih,
                                                 const float* __restrict__ bhh) {
    __shared__ __half Xs[32 * GXSTR];
    __shared__ float  Cs[32 * GCSTR];
    const int tid  = threadIdx.x;
    const int lane = tid & 31;
    const int w    = tid >> 5;
    const int wm   = w & 1;        // 2 M groups of 16 nodes
    const int wn   = w >> 1;       // 4 N groups of 64 gate cols
    const int v0   = blockIdx.x * 32;

    // stage X = [relu(neigh+cb) | h] fp16, float4 loads
    for (int q = tid; q < 512; q += 256) {
        int r = q >> 4, k4 = (q & 15) * 4;
        float4 nv = *(const float4*)&d_neigh[(size_t)(v0 + r) * D + k4];
        float4 cb = *(const float4*)&conv_b[k4];
        float4 hv = *(const float4*)&d_h[(size_t)(v0 + r) * D + k4];
        __half2 x0 = __floats2half2_rn(fmaxf(nv.x + cb.x, 0.f), fmaxf(nv.y + cb.y, 0.f));
        __half2 x1 = __floats2half2_rn(fmaxf(nv.z + cb.z, 0.f), fmaxf(nv.w + cb.w, 0.f));
        __half2 h0 = __floats2half2_rn(hv.x, hv.y);
        __half2 h1 = __floats2half2_rn(hv.z, hv.w);
        *(__half2*)&Xs[r * GXSTR + k4]          = x0;
        *(__half2*)&Xs[r * GXSTR + k4 + 2]      = x1;
        *(__half2*)&Xs[r * GXSTR + 64 + k4]     = h0;
        *(__half2*)&Xs[r * GXSTR + 64 + k4 + 2] = h1;
    }
    __syncthreads();

    const uint32_t xbase = smem_u32(Xs);
    const int a_r = lane & 15, a_c = (lane >> 4) * 8;
    const uint32_t aAddr0 = xbase + (uint32_t)((wm * 16 + a_r) * GXSTR + a_c) * 2;
    // fragment-ordered B: base for this warp's wn, indexed [j][kc][lane]
    const uint2* wf = (const uint2*)(d_WgF) + (size_t)wn * 8 * 8 * 32 + lane;

    float c[8][4];
    #pragma unroll
    for (int j = 0; j < 8; j++)
        #pragma unroll
        for (int q = 0; q < 4; q++) c[j][q] = 0.f;

    #pragma unroll
    for (int kc = 0; kc < 8; kc++) {
        uint32_t a[4];
        ldsm_x4(aAddr0 + kc * 32, a[0], a[1], a[2], a[3]);
        #pragma unroll
        for (int j = 0; j < 8; j++) {
            uint2 bv = __ldg(wf + (j * 8 + kc) * 32);
            uint32_t b[2] = { bv.x, bv.y };
            mma16816(c[j], a, b);
        }
    }

    // stage C (fp32) by direct fragment mapping
    {
        int crow = wm * 16 + (lane >> 2);
        int cc0  = wn * 64 + 2 * (lane & 3);
        #pragma unroll
        for (int j = 0; j < 8; j++) {
            int cc = cc0 + j * 8;
            *(float2*)&Cs[crow * GCSTR + cc]       = make_float2(c[j][0], c[j][1]);
            *(float2*)&Cs[(crow + 8) * GCSTR + cc] = make_float2(c[j][2], c[j][3]);
        }
    }
    __syncthreads();

    // fused gates + h update + neigh re-zero
    for (int q = tid; q < 2048; q += 256) {
        int r = q >> 6, j = q & 63;
        int v = v0 + r;
        if (v >= V_N) continue;
        const float* cr = Cs + r * GCSTR;
        float g0 = cr[j], g1 = cr[64 + j], g2 = cr[128 + j], g3 = cr[192 + j];
        float rg = 1.f / (1.f + __expf(-(g0 + __ldg(&bih[j])      + __ldg(&bhh[j]))));
        float zg = 1.f / (1.f + __expf(-(g1 + __ldg(&bih[64 + j]) + __ldg(&bhh[64 + j]))));
        float nx = g2 + __ldg(&bih[128 + j]) + rg * (g3 + __ldg(&bhh[128 + j]));
        float e2 = __expf(2.f * nx);
        float ng = 1.f - 2.f / (e2 + 1.f);     // tanh, saturates safely
        size_t gi = (size_t)v * D + j;
        float hp = d_h[gi];
        d_h[gi] = (1.f - zg) * ng + zg * hp;
        d_neigh[gi] = 0.f;
    }
}

__global__ void pred_kernel(const int* __restrict__ src, const int* __restrict__ dst,
                            const float* __restrict__ pW, const float* __restrict__ pb,
                            float* __restrict__ out) {
    int wg   = (blockIdx.x * blockDim.x + threadIdx.x) >> 5;
    int lane = threadIdx.x & 31;
    if (wg >= E_N) return;
    int se = src[wg], de = dst[wg];
    float2 a  = ((const float2*)(d_h + (size_t)se * D))[lane];
    float2 b  = ((const float2*)(d_h + (size_t)de * D))[lane];
    float2 w1 = ((const float2*)pW)[lane];
    float2 w2 = ((const float2*)pW)[32 + lane];
    float acc = a.x * w1.x + a.y * w1.y + b.x * w2.x + b.y * w2.y;
    #pragma unroll
    for (int off = 16; off > 0; off >>= 1)
        acc += __shfl_down_sync(0xffffffffu, acc, off);
    if (lane == 0) out[wg] = acc + pb[0];
}

// ---------------- launch ------------------------------------------------------
extern "C" void kernel_launch(void* const* d_in, const int* in_sizes, int n_in,
                              void* d_out, int out_size) {
    const float* node_feats = (const float*)d_in[0];
    const float* edge_feats = (const float*)d_in[1];
    const int*   src        = (const int*)d_in[2];
    const int*   dst        = (const int*)d_in[3];
    const float* proj_W     = (const float*)d_in[4];
    const float* proj_b     = (const float*)d_in[5];
    const float* en_W1      = (const float*)d_in[6];
    const float* en_b1      = (const float*)d_in[7];
    const float* en_W2      = (const float*)d_in[8];
    const float* en_b2      = (const float*)d_in[9];
    const float* conv_b     = (const float*)d_in[10];
    const float* gru_Wih    = (const float*)d_in[11];
    const float* gru_Whh    = (const float*)d_in[12];
    const float* gru_bih    = (const float*)d_in[13];
    const float* gru_bhh    = (const float*)d_in[14];
    const float* pred_W     = (const float*)d_in[15];
    const float* pred_b     = (const float*)d_in[16];
    float* out = (float*)d_out;

    static int attr_set = 0;
    if (!attr_set) {
        cudaFuncSetAttribute(ew_gemm, cudaFuncAttributeMaxDynamicSharedMemorySize, EW_SMEM);
        attr_set = 1;
    }

    prep_all<<<ZB + PB + WB, 256>>>(edge_feats, en_W1, en_b1, node_feats,
                                    proj_W, proj_b, gru_Wih, gru_Whh);   // 1
    dim3 gg(NSLABS, MGROUPS);                                            // (32, 9)
    ew_gemm<<<gg, 256, EW_SMEM>>>(en_W2, en_b2);                         // 2

    for (int s = 0; s < STEPS; s++) {
        scatter_kernel<<<E_N / 8, 256>>>(src, dst);                      // 3 on s=0
        gru_mm<<<V_PAD / 32, 256>>>(conv_b, gru_bih, gru_bhh);           // 4 on s=0 (profiled)
    }
    pred_kernel<<<E_N / 8, 256>>>(src, dst, pred_W, pred_b, out);
}

// round 13
// speedup vs baseline: 1.2670x; 1.0497x over previous
#include <cuda_runtime.h>
#include <cuda_fp16.h>
#include <cstdint>

#define V_N 20000
#define V_PAD 20032      // 313 * 64
#define E_N 40000
#define E_PAD 40064      // 313 * 128
#define NT 313           // 128-row M tiles in ew gemm
#define NIN 74
#define EIN 12
#define D 64
#define EH 128
#define DD 4096
#define STEPS 6

// ---------------- scratch (static device globals; zero-initialized) ---------
__device__ float    d_h[V_PAD * D];
__device__ float    d_neigh[V_PAD * D];
__device__ __half   d_z[E_PAD * EH];
__device__ __half   d_ew[(size_t)E_PAD * DD];
__device__ uint32_t d_WgF[4 * 8 * 8 * 64];     // fragment-ordered GRU weights (64KB)

// ---------------- asm helpers -------------------------------------------------
__device__ __forceinline__ uint32_t smem_u32(const void* p) {
    uint32_t a;
    asm("{ .reg .u64 t; cvta.to.shared.u64 t, %1; cvt.u32.u64 %0, t; }" : "=r"(a) : "l"(p));
    return a;
}
__device__ __forceinline__ void cp16(uint32_t s, const void* g) {
    asm volatile("cp.async.cg.shared.global [%0], [%1], 16;" :: "r"(s), "l"(g));
}
#define CP_COMMIT() asm volatile("cp.async.commit_group;" ::: "memory")
#define CP_WAIT0()  asm volatile("cp.async.wait_group 0;" ::: "memory")

__device__ __forceinline__ void ldsm_x4(uint32_t addr, uint32_t& r0, uint32_t& r1,
                                        uint32_t& r2, uint32_t& r3) {
    asm volatile("ldmatrix.sync.aligned.m8n8.x4.shared.b16 {%0,%1,%2,%3}, [%4];"
                 : "=r"(r0), "=r"(r1), "=r"(r2), "=r"(r3) : "r"(addr));
}
__device__ __forceinline__ void ldsm_x2(uint32_t addr, uint32_t& r0, uint32_t& r1) {
    asm volatile("ldmatrix.sync.aligned.m8n8.x2.shared.b16 {%0,%1}, [%2];"
                 : "=r"(r0), "=r"(r1) : "r"(addr));
}
__device__ __forceinline__ void mma16816(float* c, const uint32_t* a, const uint32_t* b) {
    asm volatile("mma.sync.aligned.m16n8k16.row.col.f32.f16.f16.f32 "
                 "{%0,%1,%2,%3}, {%4,%5,%6,%7}, {%8,%9}, {%0,%1,%2,%3};"
                 : "+f"(c[0]), "+f"(c[1]), "+f"(c[2]), "+f"(c[3])
                 : "r"(a[0]), "r"(a[1]), "r"(a[2]), "r"(a[3]), "r"(b[0]), "r"(b[1]));
}

// packed GRU weight value: Wg[256][128]; rows 0:64 [Wih_r|Whh_r],
// 64:128 [Wih_z|Whh_z], 128:192 [Wih_n|0], 192:256 [0|Whh_n]
__device__ __forceinline__ float wg_val(int r, int k,
                                        const float* __restrict__ Wih,
                                        const float* __restrict__ Whh) {
    if (r < 128)  return (k < 64) ? Wih[r * D + k] : Whh[r * D + (k - 64)];
    if (r < 192)  return (k < 64) ? Wih[r * D + k] : 0.f;
    return (k >= 64) ? Whh[(r - 64) * D + (k - 64)] : 0.f;
}

// ---------------- fused prep: zhid (2500 blk) + proj (1250 blk) + wg (32 blk)
#define ZB 2500
#define PB 1250
#define WB 32
__global__ void prep_all(const float* __restrict__ ef,  const float* __restrict__ W1,
                         const float* __restrict__ b1,  const float* __restrict__ nf,
                         const float* __restrict__ pW,  const float* __restrict__ pb,
                         const float* __restrict__ Wih, const float* __restrict__ Whh) {
    __shared__ char sb[24320];
    const int tid = threadIdx.x;
    const int bx  = blockIdx.x;

    if (bx < ZB) {
        float* W1s = (float*)sb;
        float* b1s = (float*)(sb + 6144);
        float* efs = (float*)(sb + 6656);
        const int e0 = bx * 16;
        for (int idx = tid; idx < EH * EIN; idx += 256) {
            int k = idx / EIN, i = idx % EIN;
            W1s[i * EH + k] = W1[idx];
        }
        for (int idx = tid; idx < 16 * EIN; idx += 256) {
            int e = idx / EIN, i = idx % EIN;
            efs[e * EIN + i] = ef[(size_t)(e0 + e) * EIN + i];
        }
        if (tid < EH) b1s[tid] = b1[tid];
        __syncthreads();
        const int k = tid & 127, g = tid >> 7;
        #pragma unroll
        for (int ee = 0; ee < 8; ee++) {
            int e = g * 8 + ee;
            float acc = b1s[k];
            #pragma unroll
            for (int i = 0; i < EIN; i++)
                acc = fmaf(W1s[i * EH + k], efs[e * EIN + i], acc);
            d_z[(size_t)(e0 + e) * EH + k] = __float2half(fmaxf(acc, 0.f));
        }
    } else if (bx < ZB + PB) {
        float* Ws  = (float*)sb;
        float* nfs = (float*)(sb + 18944);
        float* bs  = (float*)(sb + 23808);
        const int v0 = (bx - ZB) * 16;
        for (int idx = tid; idx < D * NIN; idx += 256) {
            int o = idx / NIN, i = idx % NIN;
            Ws[i * D + o] = pW[idx];
        }
        for (int idx = tid; idx < 16 * NIN; idx += 256) {
            int n = idx / NIN, i = idx % NIN;
            nfs[n * (NIN + 2) + i] = nf[(size_t)(v0 + n) * NIN + i];
        }
        if (tid < D) bs[tid] = pb[tid];
        __syncthreads();
        const int o = tid & 63, g = tid >> 6;
        #pragma unroll
        for (int nn = 0; nn < 4; nn++) {
            int n = g * 4 + nn;
            float acc = bs[o];
            #pragma unroll
            for (int i = 0; i < NIN; i++)
                acc = fmaf(Ws[i * D + o], nfs[n * (NIN + 2) + i], acc);
            d_h[(size_t)(v0 + n) * D + o] = fmaxf(acc, 0.f);
            d_neigh[(size_t)(v0 + n) * D + o] = 0.f;
        }
    } else {
        // fragment-ordered Wg for gate-in-register gru:
        // t indexes (wn, j, kc, lane); j = 2*gate_half: gate = j>>1, jh = j&1
        // B row n = gate*64 + wn*16 + jh*8 + (lane>>2)
        int t = (bx - ZB - PB) * 256 + tid;      // 0..8191
        int lane = t & 31, kc = (t >> 5) & 7, j = (t >> 8) & 7, wn = t >> 11;
        int n  = (j >> 1) * 64 + wn * 16 + (j & 1) * 8 + (lane >> 2);
        int k0 = kc * 16 + 2 * (lane & 3);
        __half2 w0 = __floats2half2_rn(wg_val(n, k0,     Wih, Whh),
                                       wg_val(n, k0 + 1, Wih, Whh));
        __half2 w1 = __floats2half2_rn(wg_val(n, k0 + 8, Wih, Whh),
                                       wg_val(n, k0 + 9, Wih, Whh));
        d_WgF[t * 2]     = *(uint32_t*)&w0;
        d_WgF[t * 2 + 1] = *(uint32_t*)&w1;
    }
}

// ---------------- ew GEMM (best measured: PTX mma, direct half2 epilogue) -----
#define ASTR 152
#define BSTR 152
#define B_BYTES   (128 * BSTR * 2)
#define A_BYTES   (128 * ASTR * 2)
#define A_OFF     B_BYTES
#define EW_SMEM   (A_OFF + A_BYTES)            // 77824 -> 2 CTAs/SM
#define NSLABS 32
#define MGROUPS 9

__global__ __launch_bounds__(256, 2) void ew_gemm(const float* __restrict__ W2,
                                                  const float* __restrict__ b2) {
    extern __shared__ char smem[];
    __half* Bs = (__half*)smem;
    __half* As = (__half*)(smem + A_OFF);
    const uint32_t sbase = smem_u32(smem);
    const int tid  = threadIdx.x;
    const int lane = tid & 31;
    const int w    = tid >> 5;
    const int wm   = w & 3;
    const int wn   = w >> 2;
    const int n0   = blockIdx.x * 128;
    const int by   = blockIdx.y;

    for (int q = tid; q < 4096; q += 256) {
        int n = q >> 5, k4 = (q & 31) * 4;
        float4 v = *(const float4*)&W2[(size_t)(n0 + n) * EH + k4];
        __half t4[4] = { __float2half(v.x), __float2half(v.y),
                         __float2half(v.z), __float2half(v.w) };
        *(uint2*)&Bs[n * BSTR + k4] = *(uint2*)t4;
    }
    for (int q = tid; q < 2048; q += 256) {
        int n = q >> 4, k = 128 + (q & 15);
        Bs[n * BSTR + k] = (k == 128) ? __float2half(b2[n0 + n]) : __half(0);
    }
    for (int q = tid; q < 2048; q += 256) {
        int r = q >> 4, k = 128 + (q & 15);
        As[r * ASTR + k] = (k == 128) ? __float2half(1.f) : __half(0);
    }
    for (int q = tid; q < 2048; q += 256) {
        int r = q >> 4, c = (q & 15) * 8;
        cp16(sbase + A_OFF + (uint32_t)(r * ASTR + c) * 2,
             &d_z[(size_t)(by * 128 + r) * EH + c]);
    }
    CP_COMMIT();

    const int a_r = lane & 15, a_c = (lane >> 4) * 8;
    const int b_r = lane & 7,  b_c = ((lane >> 3) & 1) * 8;
    const uint32_t aAddr0 = sbase + A_OFF + (uint32_t)((wm * 32 + a_r) * ASTR + a_c) * 2;
    const uint32_t bAddr0 = sbase + (uint32_t)((wn * 64 + b_r) * BSTR + b_c) * 2;

    const int TPT = (NT + MGROUPS - 1) / MGROUPS;
    for (int mt = 0; mt < TPT; mt++) {
        int t = by + MGROUPS * mt;
        if (t >= NT) break;
        CP_WAIT0();
        __syncthreads();

        float c[2][8][4];
        #pragma unroll
        for (int i = 0; i < 2; i++)
            #pragma unroll
            for (int j = 0; j < 8; j++)
                #pragma unroll
                for (int q = 0; q < 4; q++) c[i][j][q] = 0.f;

        #pragma unroll
        for (int kc = 0; kc < 9; kc++) {
            uint32_t a[2][4];
            #pragma unroll
            for (int i = 0; i < 2; i++)
                ldsm_x4(aAddr0 + (uint32_t)(i * 16 * ASTR + kc * 16) * 2,
                        a[i][0], a[i][1], a[i][2], a[i][3]);
            uint32_t b[8][2];
            #pragma unroll
            for (int j = 0; j < 8; j++)
                ldsm_x2(bAddr0 + (uint32_t)(j * 8 * BSTR + kc * 16) * 2,
                        b[j][0], b[j][1]);
            #pragma unroll
            for (int i = 0; i < 2; i++)
                #pragma unroll
                for (int j = 0; j < 8; j++)
                    mma16816(c[i][j], a[i], b[j]);
        }
        __syncthreads();

        int tn = t + MGROUPS;
        if (tn < NT) {
            for (int q = tid; q < 2048; q += 256) {
                int r = q >> 4, cc = (q & 15) * 8;
                cp16(sbase + A_OFF + (uint32_t)(r * ASTR + cc) * 2,
                     &d_z[(size_t)(tn * 128 + r) * EH + cc]);
            }
            CP_COMMIT();
        }

        const int rbase = t * 128 + wm * 32 + (lane >> 2);
        const int cbase = n0 + wn * 64 + 2 * (lane & 3);
        #pragma unroll
        for (int i = 0; i < 2; i++) {
            size_t rowo = (size_t)(rbase + i * 16) * DD;
            #pragma unroll
            for (int j = 0; j < 8; j++) {
                int col = cbase + j * 8;
                *(__half2*)&d_ew[rowo + col] =
                    __floats2half2_rn(c[i][j][0], c[i][j][1]);
                *(__half2*)&d_ew[rowo + 8 * DD + col] =
                    __floats2half2_rn(c[i][j][2], c[i][j][3]);
            }
        }
    }
}

// ---------------- per-step kernels -------------------------------------------
// warp per edge, LDG.128 rows (at HBM/LTS ceiling per R9 ncu)
__global__ void scatter_kernel(const int* __restrict__ src, const int* __restrict__ dst) {
    int wg   = (blockIdx.x * blockDim.x + threadIdx.x) >> 5;
    int lane = threadIdx.x & 31;
    if (wg >= E_N) return;
    int se = __ldg(&src[wg]), de = __ldg(&dst[wg]);
    float2 hv = ((const float2*)(d_h + (size_t)se * D))[lane];
    const int4* W4 = (const int4*)(d_ew + (size_t)wg * DD);
    const int rsub = lane >> 3;
    const int cg   = lane & 7;
    float acc[8] = {0.f, 0.f, 0.f, 0.f, 0.f, 0.f, 0.f, 0.f};

    #pragma unroll
    for (int i = 0; i < 16; i++) {
        int r = 4 * i + rsub;
        int4 wv = __ldg(&W4[r * 8 + cg]);
        float hx = __shfl_sync(0xffffffffu, hv.x, 2 * i + (lane >> 4));
        float hy = __shfl_sync(0xffffffffu, hv.y, 2 * i + (lane >> 4));
        float hr = (rsub & 1) ? hy : hx;
        const __half2* wh = (const __half2*)&wv;
        #pragma unroll
        for (int q = 0; q < 4; q++) {
            float2 f = __half22float2(wh[q]);
            acc[2 * q]     = fmaf(hr, f.x, acc[2 * q]);
            acc[2 * q + 1] = fmaf(hr, f.y, acc[2 * q + 1]);
        }
    }
    #pragma unroll
    for (int j = 0; j < 8; j++) {
        acc[j] += __shfl_xor_sync(0xffffffffu, acc[j], 8);
        acc[j] += __shfl_xor_sync(0xffffffffu, acc[j], 16);
    }
    if (lane < 8) {
        float* nb = d_neigh + (size_t)de * D + lane * 8;
        #pragma unroll
        for (int j = 0; j < 8; j++) atomicAdd(nb + j, acc[j]);
    }
}

// GRU v4: gates fully in registers. Warp wn owns the SAME 16 columns of all
// four gate blocks (j = gate*2 + colhalf), so after the mma each thread holds
// g_r/g_z/g_in/g_hn for its (row, col) pairs -> no Cs staging, no 2nd sync.
#define GXSTR 136
__global__ __launch_bounds__(256, 4) void gru_mm(const float* __restrict__ conv_b,
                                                 const float* __restrict__ bih,
                                                 const float* __restrict__ bhh) {
    __shared__ __half Xs[32 * GXSTR];
    const int tid  = threadIdx.x;
    const int lane = tid & 31;
    const int w    = tid >> 5;
    const int wm   = w & 1;        // 2 M groups of 16 nodes
    const int wn   = w >> 1;       // 4 N groups of 16 gate cols (x4 gates)
    const int v0   = blockIdx.x * 32;

    // stage X = [relu(neigh+cb) | h] fp16, float4 loads
    for (int q = tid; q < 512; q += 256) {
        int r = q >> 4, k4 = (q & 15) * 4;
        float4 nv = *(const float4*)&d_neigh[(size_t)(v0 + r) * D + k4];
        float4 cb = *(const float4*)&conv_b[k4];
        float4 hv = *(const float4*)&d_h[(size_t)(v0 + r) * D + k4];
        __half2 x0 = __floats2half2_rn(fmaxf(nv.x + cb.x, 0.f), fmaxf(nv.y + cb.y, 0.f));
        __half2 x1 = __floats2half2_rn(fmaxf(nv.z + cb.z, 0.f), fmaxf(nv.w + cb.w, 0.f));
        __half2 h0 = __floats2half2_rn(hv.x, hv.y);
        __half2 h1 = __floats2half2_rn(hv.z, hv.w);
        *(__half2*)&Xs[r * GXSTR + k4]          = x0;
        *(__half2*)&Xs[r * GXSTR + k4 + 2]      = x1;
        *(__half2*)&Xs[r * GXSTR + 64 + k4]     = h0;
        *(__half2*)&Xs[r * GXSTR + 64 + k4 + 2] = h1;
    }
    __syncthreads();

    const uint32_t xbase = smem_u32(Xs);
    const int a_r = lane & 15, a_c = (lane >> 4) * 8;
    const uint32_t aAddr0 = xbase + (uint32_t)((wm * 16 + a_r) * GXSTR + a_c) * 2;
    const uint2* wf = (const uint2*)(d_WgF) + (size_t)wn * 8 * 8 * 32 + lane;

    float c[8][4];
    #pragma unroll
    for (int j = 0; j < 8; j++)
        #pragma unroll
        for (int q = 0; q < 4; q++) c[j][q] = 0.f;

    #pragma unroll
    for (int kc = 0; kc < 8; kc++) {
        uint32_t a[4];
        ldsm_x4(aAddr0 + kc * 32, a[0], a[1], a[2], a[3]);
        #pragma unroll
        for (int j = 0; j < 8; j++) {
            uint2 bv = __ldg(wf + (j * 8 + kc) * 32);
            uint32_t b[2] = { bv.x, bv.y };
            mma16816(c[j], a, b);
        }
    }

    // gates in registers: thread covers rows {crow, crow+8}, cols
    // {c0, c0+1, c0+8, c0+9} of gate-column block wn*16..wn*16+15.
    const int crow = wm * 16 + (lane >> 2);
    const int c0   = wn * 16 + 2 * (lane & 3);
    #pragma unroll
    for (int jh = 0; jh < 2; jh++) {
        const int cb = c0 + jh * 8;          // even column base
        float sr0 = __ldg(&bih[cb])       + __ldg(&bhh[cb]);
        float sr1 = __ldg(&bih[cb + 1])   + __ldg(&bhh[cb + 1]);
        float sz0 = __ldg(&bih[64 + cb])  + __ldg(&bhh[64 + cb]);
        float sz1 = __ldg(&bih[64 + cb + 1]) + __ldg(&bhh[64 + cb + 1]);
        float bi0 = __ldg(&bih[128 + cb]),     bi1 = __ldg(&bih[128 + cb + 1]);
        float bh0 = __ldg(&bhh[128 + cb]),     bh1 = __ldg(&bhh[128 + cb + 1]);
        #pragma unroll
        for (int pr = 0; pr < 2; pr++) {
            int v = v0 + crow + pr * 8;
            if (v >= V_N) continue;
            size_t gi = (size_t)v * D + cb;
            float2 hp = *(float2*)&d_h[gi];
            int q0 = pr * 2;
            float rg0 = 1.f / (1.f + __expf(-(c[jh][q0]     + sr0)));
            float rg1 = 1.f / (1.f + __expf(-(c[jh][q0 + 1] + sr1)));
            float zg0 = 1.f / (1.f + __expf(-(c[2 + jh][q0]     + sz0)));
            float zg1 = 1.f / (1.f + __expf(-(c[2 + jh][q0 + 1] + sz1)));
            float nx0 = c[4 + jh][q0]     + bi0 + rg0 * (c[6 + jh][q0]     + bh0);
            float nx1 = c[4 + jh][q0 + 1] + bi1 + rg1 * (c[6 + jh][q0 + 1] + bh1);
            float e0 = __expf(2.f * nx0), e1 = __expf(2.f * nx1);
            float ng0 = 1.f - 2.f / (e0 + 1.f);
            float ng1 = 1.f - 2.f / (e1 + 1.f);
            float2 hn;
            hn.x = (1.f - zg0) * ng0 + zg0 * hp.x;
            hn.y = (1.f - zg1) * ng1 + zg1 * hp.y;
            *(float2*)&d_h[gi] = hn;
            *(float2*)&d_neigh[gi] = make_float2(0.f, 0.f);
        }
    }
}

__global__ void pred_kernel(const int* __restrict__ src, const int* __restrict__ dst,
                            const float* __restrict__ pW, const float* __restrict__ pb,
                            float* __restrict__ out) {
    int wg   = (blockIdx.x * blockDim.x + threadIdx.x) >> 5;
    int lane = threadIdx.x & 31;
    if (wg >= E_N) return;
    int se = src[wg], de = dst[wg];
    float2 a  = ((const float2*)(d_h + (size_t)se * D))[lane];
    float2 b  = ((const float2*)(d_h + (size_t)de * D))[lane];
    float2 w1 = ((const float2*)pW)[lane];
    float2 w2 = ((const float2*)pW)[32 + lane];
    float acc = a.x * w1.x + a.y * w1.y + b.x * w2.x + b.y * w2.y;
    #pragma unroll
    for (int off = 16; off > 0; off >>= 1)
        acc += __shfl_down_sync(0xffffffffu, acc, off);
    if (lane == 0) out[wg] = acc + pb[0];
}

// ---------------- launch ------------------------------------------------------
extern "C" void kernel_launch(void* const* d_in, const int* in_sizes, int n_in,
                              void* d_out, int out_size) {
    const float* node_feats = (const float*)d_in[0];
    const float* edge_feats = (const float*)d_in[1];
    const int*   src        = (const int*)d_in[2];
    const int*   dst        = (const int*)d_in[3];
    const float* proj_W     = (const float*)d_in[4];
    const float* proj_b     = (const float*)d_in[5];
    const float* en_W1      = (const float*)d_in[6];
    const float* en_b1      = (const float*)d_in[7];
    const float* en_W2      = (const float*)d_in[8];
    const float* en_b2      = (const float*)d_in[9];
    const float* conv_b     = (const float*)d_in[10];
    const float* gru_Wih    = (const float*)d_in[11];
    const float* gru_Whh    = (const float*)d_in[12];
    const float* gru_bih    = (const float*)d_in[13];
    const float* gru_bhh    = (const float*)d_in[14];
    const float* pred_W     = (const float*)d_in[15];
    const float* pred_b     = (const float*)d_in[16];
    float* out = (float*)d_out;

    static int attr_set = 0;
    if (!attr_set) {
        cudaFuncSetAttribute(ew_gemm, cudaFuncAttributeMaxDynamicSharedMemorySize, EW_SMEM);
        attr_set = 1;
    }

    prep_all<<<ZB + PB + WB, 256>>>(edge_feats, en_W1, en_b1, node_feats,
                                    proj_W, proj_b, gru_Wih, gru_Whh);   // 1
    dim3 gg(NSLABS, MGROUPS);                                            // (32, 9)
    ew_gemm<<<gg, 256, EW_SMEM>>>(en_W2, en_b2);                         // 2

    for (int s = 0; s < STEPS; s++) {
        scatter_kernel<<<E_N / 8, 256>>>(src, dst);                      // 3 on s=0
        gru_mm<<<V_PAD / 32, 256>>>(conv_b, gru_bih, gru_bhh);           // 4 on s=0 (profiled)
    }
    pred_kernel<<<E_N / 8, 256>>>(src, dst, pred_W, pred_b, out);
}

// round 15
// speedup vs baseline: 1.3549x; 1.0694x over previous
#include <cuda_runtime.h>
#include <cuda_fp16.h>
#include <cstdint>

#define V_N 20000
#define V_PAD 20032      // 313 * 64
#define E_N 40000
#define E_PAD 40064      // 313 * 128
#define NT 313           // 128-row M tiles in ew gemm
#define NIN 74
#define EIN 12
#define D 64
#define EH 128
#define DD 4096
#define STEPS 6

// ---------------- scratch (static device globals; zero-initialized) ---------
__device__ float    d_h[V_PAD * D];
__device__ float    d_neigh[V_PAD * D];
__device__ __half   d_z[E_PAD * EH];
__device__ __half   d_ew[(size_t)E_PAD * DD];
__device__ uint32_t d_WgF[4 * 8 * 8 * 64];     // fragment-ordered GRU weights (64KB)

// ---------------- asm helpers -------------------------------------------------
__device__ __forceinline__ uint32_t smem_u32(const void* p) {
    uint32_t a;
    asm("{ .reg .u64 t; cvta.to.shared.u64 t, %1; cvt.u32.u64 %0, t; }" : "=r"(a) : "l"(p));
    return a;
}
__device__ __forceinline__ void cp16(uint32_t s, const void* g) {
    asm volatile("cp.async.cg.shared.global [%0], [%1], 16;" :: "r"(s), "l"(g));
}
#define CP_COMMIT() asm volatile("cp.async.commit_group;" ::: "memory")
#define CP_WAIT0()  asm volatile("cp.async.wait_group 0;" ::: "memory")

__device__ __forceinline__ void ldsm_x4(uint32_t addr, uint32_t& r0, uint32_t& r1,
                                        uint32_t& r2, uint32_t& r3) {
    asm volatile("ldmatrix.sync.aligned.m8n8.x4.shared.b16 {%0,%1,%2,%3}, [%4];"
                 : "=r"(r0), "=r"(r1), "=r"(r2), "=r"(r3) : "r"(addr));
}
__device__ __forceinline__ void mma16816(float* c, const uint32_t* a, const uint32_t* b) {
    asm volatile("mma.sync.aligned.m16n8k16.row.col.f32.f16.f16.f32 "
                 "{%0,%1,%2,%3}, {%4,%5,%6,%7}, {%8,%9}, {%0,%1,%2,%3};"
                 : "+f"(c[0]), "+f"(c[1]), "+f"(c[2]), "+f"(c[3])
                 : "r"(a[0]), "r"(a[1]), "r"(a[2]), "r"(a[3]), "r"(b[0]), "r"(b[1]));
}

// packed GRU weight value: Wg[256][128]; rows 0:64 [Wih_r|Whh_r],
// 64:128 [Wih_z|Whh_z], 128:192 [Wih_n|0], 192:256 [0|Whh_n]
__device__ __forceinline__ float wg_val(int r, int k,
                                        const float* __restrict__ Wih,
                                        const float* __restrict__ Whh) {
    if (r < 128)  return (k < 64) ? Wih[r * D + k] : Whh[r * D + (k - 64)];
    if (r < 192)  return (k < 64) ? Wih[r * D + k] : 0.f;
    return (k >= 64) ? Whh[(r - 64) * D + (k - 64)] : 0.f;
}

// ---------------- fused prep: zhid (2500 blk) + proj (1250 blk) + wg (32 blk)
#define ZB 2500
#define PB 1250
#define WB 32
__global__ void prep_all(const float* __restrict__ ef,  const float* __restrict__ W1,
                         const float* __restrict__ b1,  const float* __restrict__ nf,
                         const float* __restrict__ pW,  const float* __restrict__ pb,
                         const float* __restrict__ Wih, const float* __restrict__ Whh) {
    __shared__ char sb[24320];
    const int tid = threadIdx.x;
    const int bx  = blockIdx.x;

    if (bx < ZB) {
        float* W1s = (float*)sb;
        float* b1s = (float*)(sb + 6144);
        float* efs = (float*)(sb + 6656);
        const int e0 = bx * 16;
        for (int idx = tid; idx < EH * EIN; idx += 256) {
            int k = idx / EIN, i = idx % EIN;
            W1s[i * EH + k] = W1[idx];
        }
        for (int idx = tid; idx < 16 * EIN; idx += 256) {
            int e = idx / EIN, i = idx % EIN;
            efs[e * EIN + i] = ef[(size_t)(e0 + e) * EIN + i];
        }
        if (tid < EH) b1s[tid] = b1[tid];
        __syncthreads();
        const int k = tid & 127, g = tid >> 7;
        #pragma unroll
        for (int ee = 0; ee < 8; ee++) {
            int e = g * 8 + ee;
            float acc = b1s[k];
            #pragma unroll
            for (int i = 0; i < EIN; i++)
                acc = fmaf(W1s[i * EH + k], efs[e * EIN + i], acc);
            d_z[(size_t)(e0 + e) * EH + k] = __float2half(fmaxf(acc, 0.f));
        }
    } else if (bx < ZB + PB) {
        float* Ws  = (float*)sb;
        float* nfs = (float*)(sb + 18944);
        float* bs  = (float*)(sb + 23808);
        const int v0 = (bx - ZB) * 16;
        for (int idx = tid; idx < D * NIN; idx += 256) {
            int o = idx / NIN, i = idx % NIN;
            Ws[i * D + o] = pW[idx];
        }
        for (int idx = tid; idx < 16 * NIN; idx += 256) {
            int n = idx / NIN, i = idx % NIN;
            nfs[n * (NIN + 2) + i] = nf[(size_t)(v0 + n) * NIN + i];
        }
        if (tid < D) bs[tid] = pb[tid];
        __syncthreads();
        const int o = tid & 63, g = tid >> 6;
        #pragma unroll
        for (int nn = 0; nn < 4; nn++) {
            int n = g * 4 + nn;
            float acc = bs[o];
            #pragma unroll
            for (int i = 0; i < NIN; i++)
                acc = fmaf(Ws[i * D + o], nfs[n * (NIN + 2) + i], acc);
            d_h[(size_t)(v0 + n) * D + o] = fmaxf(acc, 0.f);
            d_neigh[(size_t)(v0 + n) * D + o] = 0.f;
        }
    } else {
        // fragment-ordered Wg for gate-in-register gru
        int t = (bx - ZB - PB) * 256 + tid;      // 0..8191
        int lane = t & 31, kc = (t >> 5) & 7, j = (t >> 8) & 7, wn = t >> 11;
        int n  = (j >> 1) * 64 + wn * 16 + (j & 1) * 8 + (lane >> 2);
        int k0 = kc * 16 + 2 * (lane & 3);
        __half2 w0 = __floats2half2_rn(wg_val(n, k0,     Wih, Whh),
                                       wg_val(n, k0 + 1, Wih, Whh));
        __half2 w1 = __floats2half2_rn(wg_val(n, k0 + 8, Wih, Whh),
                                       wg_val(n, k0 + 9, Wih, Whh));
        d_WgF[t * 2]     = *(uint32_t*)&w0;
        d_WgF[t * 2 + 1] = *(uint32_t*)&w1;
    }
}

// ---------------- ew GEMM v5: K=128, ldsm_x4 B pairs, STG.64 paired epilogue --
// C[E_PAD,4096] = z @ W2^T + b2 (bias in epilogue, fp32)
#define ASTR 136
#define BSTR 152
#define B_BYTES   (128 * BSTR * 2)             // 38912
#define A_BYTES   (128 * ASTR * 2)             // 34816
#define A_OFF     B_BYTES
#define BIAS_OFF  (A_OFF + A_BYTES)            // 73728
#define EW_SMEM   (BIAS_OFF + 512)             // 74240 -> 2 CTAs/SM
#define NSLABS 32
#define MGROUPS 9

__global__ __launch_bounds__(256, 2) void ew_gemm(const float* __restrict__ W2,
                                                  const float* __restrict__ b2) {
    extern __shared__ char smem[];
    __half* Bs     = (__half*)smem;
    float*  bias_s = (float*)(smem + BIAS_OFF);
    const uint32_t sbase = smem_u32(smem);
    const int tid  = threadIdx.x;
    const int lane = tid & 31;
    const int w    = tid >> 5;
    const int wm   = w & 3;        // 4 M groups of 32 rows
    const int wn   = w >> 2;       // 2 N groups of 64 cols
    const int n0   = blockIdx.x * 128;
    const int by   = blockIdx.y;

    // B slab: 128 N-rows x 128 K (f32 -> f16)
    for (int q = tid; q < 4096; q += 256) {
        int n = q >> 5, k4 = (q & 31) * 4;
        float4 v = *(const float4*)&W2[(size_t)(n0 + n) * EH + k4];
        __half t4[4] = { __float2half(v.x), __float2half(v.y),
                         __float2half(v.z), __float2half(v.w) };
        *(uint2*)&Bs[n * BSTR + k4] = *(uint2*)t4;
    }
    if (tid < 128) bias_s[tid] = b2[n0 + tid];
    // prefetch first A tile
    for (int q = tid; q < 2048; q += 256) {
        int r = q >> 4, c = (q & 15) * 8;
        cp16(sbase + A_OFF + (uint32_t)(r * ASTR + c) * 2,
             &d_z[(size_t)(by * 128 + r) * EH + c]);
    }
    CP_COMMIT();

    // ldsm lane addressing
    const int a_r = lane & 15, a_c = (lane >> 4) * 8;
    const uint32_t aAddr0 = sbase + A_OFF + (uint32_t)((wm * 32 + a_r) * ASTR + a_c) * 2;
    // B x4 j-pair: lanes 0-7 j0/klo, 8-15 j0/khi, 16-23 j1/klo, 24-31 j1/khi
    const int bm   = lane >> 3;                       // matrix index 0..3
    const int b_n  = ((bm >> 1) & 1) * 8 + (lane & 7);  // row within jpair block
    const int b_k  = (bm & 1) * 8;
    const uint32_t bAddr0 = sbase + (uint32_t)((wn * 64 + b_n) * BSTR + b_k) * 2;

    const bool ev = !(lane & 1);
    const int TPT = (NT + MGROUPS - 1) / MGROUPS;
    for (int mt = 0; mt < TPT; mt++) {
        int t = by + MGROUPS * mt;
        if (t >= NT) break;
        CP_WAIT0();
        __syncthreads();                      // A ready

        float c[2][8][4];
        #pragma unroll
        for (int i = 0; i < 2; i++)
            #pragma unroll
            for (int j = 0; j < 8; j++)
                #pragma unroll
                for (int q = 0; q < 4; q++) c[i][j][q] = 0.f;

        #pragma unroll
        for (int kc = 0; kc < 8; kc++) {
            uint32_t a[2][4];
            #pragma unroll
            for (int i = 0; i < 2; i++)
                ldsm_x4(aAddr0 + (uint32_t)(i * 16 * ASTR + kc * 16) * 2,
                        a[i][0], a[i][1], a[i][2], a[i][3]);
            #pragma unroll
            for (int jp = 0; jp < 4; jp++) {
                uint32_t b0, b1, b2r, b3;
                ldsm_x4(bAddr0 + (uint32_t)(jp * 16 * BSTR + kc * 16) * 2,
                        b0, b1, b2r, b3);
                uint32_t bj0[2] = { b0, b1 };
                uint32_t bj1[2] = { b2r, b3 };
                #pragma unroll
                for (int i = 0; i < 2; i++) {
                    mma16816(c[i][2 * jp],     a[i], bj0);
                    mma16816(c[i][2 * jp + 1], a[i], bj1);
                }
            }
        }
        __syncthreads();                      // A consumed

        int tn = t + MGROUPS;                 // prefetch next (overlaps epilogue)
        if (tn < NT) {
            for (int q = tid; q < 2048; q += 256) {
                int r = q >> 4, cc = (q & 15) * 8;
                cp16(sbase + A_OFF + (uint32_t)(r * ASTR + cc) * 2,
                     &d_z[(size_t)(tn * 128 + r) * EH + cc]);
            }
            CP_COMMIT();
        }

        // epilogue: bias + paired-shuffle -> STG.64, full 32B sectors per row
        const int p_own  = lane & 3;              // own col-pair within 8-col j
        const int rbase  = t * 128 + wm * 32 + (lane >> 2);
        const int j_out  = lane & 1;              // offset within j-pair
        const int cchunk = (lane >> 1) & 1;       // 4-col chunk
        #pragma unroll
        for (int jp = 0; jp < 4; jp++) {
            const int j0 = 2 * jp;
            float2 bj0 = *(float2*)&bias_s[(j0)     * 8 + 2 * p_own];
            float2 bj1 = *(float2*)&bias_s[(j0 + 1) * 8 + 2 * p_own];
            #pragma unroll
            for (int i = 0; i < 2; i++) {
                __half2 h0lo = __floats2half2_rn(c[i][j0][0] + bj0.x, c[i][j0][1] + bj0.y);
                __half2 h0hi = __floats2half2_rn(c[i][j0][2] + bj0.x, c[i][j0][3] + bj0.y);
                __half2 h1lo = __floats2half2_rn(c[i][j0+1][0] + bj1.x, c[i][j0+1][1] + bj1.y);
                __half2 h1hi = __floats2half2_rn(c[i][j0+1][2] + bj1.x, c[i][j0+1][3] + bj1.y);
                // even lane sends j1, odd sends j0
                uint32_t slo = ev ? *(uint32_t*)&h1lo : *(uint32_t*)&h0lo;
                uint32_t shi = ev ? *(uint32_t*)&h1hi : *(uint32_t*)&h0hi;
                uint32_t rlo = __shfl_sync(0xffffffffu, slo, lane ^ 1);
                uint32_t rhi = __shfl_sync(0xffffffffu, shi, lane ^ 1);
                uint32_t klo = ev ? *(uint32_t*)&h0lo : *(uint32_t*)&h1lo;
                uint32_t khi = ev ? *(uint32_t*)&h0hi : *(uint32_t*)&h1hi;
                uint2 outlo = ev ? make_uint2(klo, rlo) : make_uint2(rlo, klo);
                uint2 outhi = ev ? make_uint2(khi, rhi) : make_uint2(rhi, khi);
                int col = n0 + wn * 64 + (j0 + j_out) * 8 + 4 * cchunk;
                size_t rowo = (size_t)(rbase + i * 16) * DD + col;
                *(uint2*)&d_ew[rowo]          = outlo;
                *(uint2*)&d_ew[rowo + 8 * DD] = outhi;
            }
        }
    }
}

// ---------------- per-step kernels -------------------------------------------
// warp per edge, LDG.128 rows (at HBM/LTS ceiling per R9 ncu)
__global__ void scatter_kernel(const int* __restrict__ src, const int* __restrict__ dst) {
    int wg   = (blockIdx.x * blockDim.x + threadIdx.x) >> 5;
    int lane = threadIdx.x & 31;
    if (wg >= E_N) return;
    int se = __ldg(&src[wg]), de = __ldg(&dst[wg]);
    float2 hv = ((const float2*)(d_h + (size_t)se * D))[lane];
    const int4* W4 = (const int4*)(d_ew + (size_t)wg * DD);
    const int rsub = lane >> 3;
    const int cg   = lane & 7;
    float acc[8] = {0.f, 0.f, 0.f, 0.f, 0.f, 0.f, 0.f, 0.f};

    #pragma unroll
    for (int i = 0; i < 16; i++) {
        int r = 4 * i + rsub;
        int4 wv = __ldg(&W4[r * 8 + cg]);
        float hx = __shfl_sync(0xffffffffu, hv.x, 2 * i + (lane >> 4));
        float hy = __shfl_sync(0xffffffffu, hv.y, 2 * i + (lane >> 4));
        float hr = (rsub & 1) ? hy : hx;
        const __half2* wh = (const __half2*)&wv;
        #pragma unroll
        for (int q = 0; q < 4; q++) {
            float2 f = __half22float2(wh[q]);
            acc[2 * q]     = fmaf(hr, f.x, acc[2 * q]);
            acc[2 * q + 1] = fmaf(hr, f.y, acc[2 * q + 1]);
        }
    }
    #pragma unroll
    for (int j = 0; j < 8; j++) {
        acc[j] += __shfl_xor_sync(0xffffffffu, acc[j], 8);
        acc[j] += __shfl_xor_sync(0xffffffffu, acc[j], 16);
    }
    if (lane < 8) {
        float* nb = d_neigh + (size_t)de * D + lane * 8;
        #pragma unroll
        for (int j = 0; j < 8; j++) atomicAdd(nb + j, acc[j]);
    }
}

// GRU v4: gates fully in registers (R13 best)
#define GXSTR 136
__global__ __launch_bounds__(256, 4) void gru_mm(const float* __restrict__ conv_b,
                                                 const float* __restrict__ bih,
                                                 const float* __restrict__ bhh) {
    __shared__ __half Xs[32 * GXSTR];
    const int tid  = threadIdx.x;
    const int lane = tid & 31;
    const int w    = tid >> 5;
    const int wm   = w & 1;
    const int wn   = w >> 1;
    const int v0   = blockIdx.x * 32;

    for (int q = tid; q < 512; q += 256) {
        int r = q >> 4, k4 = (q & 15) * 4;
        float4 nv = *(const float4*)&d_neigh[(size_t)(v0 + r) * D + k4];
        float4 cb = *(const float4*)&conv_b[k4];
        float4 hv = *(const float4*)&d_h[(size_t)(v0 + r) * D + k4];
        __half2 x0 = __floats2half2_rn(fmaxf(nv.x + cb.x, 0.f), fmaxf(nv.y + cb.y, 0.f));
        __half2 x1 = __floats2half2_rn(fmaxf(nv.z + cb.z, 0.f), fmaxf(nv.w + cb.w, 0.f));
        __half2 h0 = __floats2half2_rn(hv.x, hv.y);
        __half2 h1 = __floats2half2_rn(hv.z, hv.w);
        *(__half2*)&Xs[r * GXSTR + k4]          = x0;
        *(__half2*)&Xs[r * GXSTR + k4 + 2]      = x1;
        *(__half2*)&Xs[r * GXSTR + 64 + k4]     = h0;
        *(__half2*)&Xs[r * GXSTR + 64 + k4 + 2] = h1;
    }
    __syncthreads();

    const uint32_t xbase = smem_u32(Xs);
    const int a_r = lane & 15, a_c = (lane >> 4) * 8;
    const uint32_t aAddr0 = xbase + (uint32_t)((wm * 16 + a_r) * GXSTR + a_c) * 2;
    const uint2* wf = (const uint2*)(d_WgF) + (size_t)wn * 8 * 8 * 32 + lane;

    float c[8][4];
    #pragma unroll
    for (int j = 0; j < 8; j++)
        #pragma unroll
        for (int q = 0; q < 4; q++) c[j][q] = 0.f;

    #pragma unroll
    for (int kc = 0; kc < 8; kc++) {
        uint32_t a[4];
        ldsm_x4(aAddr0 + kc * 32, a[0], a[1], a[2], a[3]);
        #pragma unroll
        for (int j = 0; j < 8; j++) {
            uint2 bv = __ldg(wf + (j * 8 + kc) * 32);
            uint32_t b[2] = { bv.x, bv.y };
            mma16816(c[j], a, b);
        }
    }

    const int crow = wm * 16 + (lane >> 2);
    const int c0   = wn * 16 + 2 * (lane & 3);
    #pragma unroll
    for (int jh = 0; jh < 2; jh++) {
        const int cb = c0 + jh * 8;
        float sr0 = __ldg(&bih[cb])       + __ldg(&bhh[cb]);
        float sr1 = __ldg(&bih[cb + 1])   + __ldg(&bhh[cb + 1]);
        float sz0 = __ldg(&bih[64 + cb])  + __ldg(&bhh[64 + cb]);
        float sz1 = __ldg(&bih[64 + cb + 1]) + __ldg(&bhh[64 + cb + 1]);
        float bi0 = __ldg(&bih[128 + cb]),     bi1 = __ldg(&bih[128 + cb + 1]);
        float bh0 = __ldg(&bhh[128 + cb]),     bh1 = __ldg(&bhh[128 + cb + 1]);
        #pragma unroll
        for (int pr = 0; pr < 2; pr++) {
            int v = v0 + crow + pr * 8;
            if (v >= V_N) continue;
            size_t gi = (size_t)v * D + cb;
            float2 hp = *(float2*)&d_h[gi];
            int q0 = pr * 2;
            float rg0 = 1.f / (1.f + __expf(-(c[jh][q0]     + sr0)));
            float rg1 = 1.f / (1.f + __expf(-(c[jh][q0 + 1] + sr1)));
            float zg0 = 1.f / (1.f + __expf(-(c[2 + jh][q0]     + sz0)));
            float zg1 = 1.f / (1.f + __expf(-(c[2 + jh][q0 + 1] + sz1)));
            float nx0 = c[4 + jh][q0]     + bi0 + rg0 * (c[6 + jh][q0]     + bh0);
            float nx1 = c[4 + jh][q0 + 1] + bi1 + rg1 * (c[6 + jh][q0 + 1] + bh1);
            float e0 = __expf(2.f * nx0), e1 = __expf(2.f * nx1);
            float ng0 = 1.f - 2.f / (e0 + 1.f);
            float ng1 = 1.f - 2.f / (e1 + 1.f);
            float2 hn;
            hn.x = (1.f - zg0) * ng0 + zg0 * hp.x;
            hn.y = (1.f - zg1) * ng1 + zg1 * hp.y;
            *(float2*)&d_h[gi] = hn;
            *(float2*)&d_neigh[gi] = make_float2(0.f, 0.f);
        }
    }
}

__global__ void pred_kernel(const int* __restrict__ src, const int* __restrict__ dst,
                            const float* __restrict__ pW, const float* __restrict__ pb,
                            float* __restrict__ out) {
    int wg   = (blockIdx.x * blockDim.x + threadIdx.x) >> 5;
    int lane = threadIdx.x & 31;
    if (wg >= E_N) return;
    int se = src[wg], de = dst[wg];
    float2 a  = ((const float2*)(d_h + (size_t)se * D))[lane];
    float2 b  = ((const float2*)(d_h + (size_t)de * D))[lane];
    float2 w1 = ((const float2*)pW)[lane];
    float2 w2 = ((const float2*)pW)[32 + lane];
    float acc = a.x * w1.x + a.y * w1.y + b.x * w2.x + b.y * w2.y;
    #pragma unroll
    for (int off = 16; off > 0; off >>= 1)
        acc += __shfl_down_sync(0xffffffffu, acc, off);
    if (lane == 0) out[wg] = acc + pb[0];
}

// ---------------- launch ------------------------------------------------------
extern "C" void kernel_launch(void* const* d_in, const int* in_sizes, int n_in,
                              void* d_out, int out_size) {
    const float* node_feats = (const float*)d_in[0];
    const float* edge_feats = (const float*)d_in[1];
    const int*   src        = (const int*)d_in[2];
    const int*   dst        = (const int*)d_in[3];
    const float* proj_W     = (const float*)d_in[4];
    const float* proj_b     = (const float*)d_in[5];
    const float* en_W1      = (const float*)d_in[6];
    const float* en_b1      = (const float*)d_in[7];
    const float* en_W2      = (const float*)d_in[8];
    const float* en_b2      = (const float*)d_in[9];
    const float* conv_b     = (const float*)d_in[10];
    const float* gru_Wih    = (const float*)d_in[11];
    const float* gru_Whh    = (const float*)d_in[12];
    const float* gru_bih    = (const float*)d_in[13];
    const float* gru_bhh    = (const float*)d_in[14];
    const float* pred_W     = (const float*)d_in[15];
    const float* pred_b     = (const float*)d_in[16];
    float* out = (float*)d_out;

    static int attr_set = 0;
    if (!attr_set) {
        cudaFuncSetAttribute(ew_gemm, cudaFuncAttributeMaxDynamicSharedMemorySize, EW_SMEM);
        attr_set = 1;
    }

    prep_all<<<ZB + PB + WB, 256>>>(edge_feats, en_W1, en_b1, node_feats,
                                    proj_W, proj_b, gru_Wih, gru_Whh);   // 1
    dim3 gg(NSLABS, MGROUPS);                                            // (32, 9)
    ew_gemm<<<gg, 256, EW_SMEM>>>(en_W2, en_b2);                         // 2 — next profile target via slot shift below

    for (int s = 0; s < STEPS; s++) {
        scatter_kernel<<<E_N / 8, 256>>>(src, dst);                      // 3 on s=0
        gru_mm<<<V_PAD / 32, 256>>>(conv_b, gru_bih, gru_bhh);           // 4 on s=0
    }
    pred_kernel<<<E_N / 8, 256>>>(src, dst, pred_W, pred_b, out);
}

// round 16
// speedup vs baseline: 1.3716x; 1.0123x over previous
#include <cuda_runtime.h>
#include <cuda_fp16.h>
#include <cstdint>

#define V_N 20000
#define V_PAD 20032      // 313 * 64
#define E_N 40000
#define E_PAD 40064      // 313 * 128
#define NT 313           // 128-row M tiles in ew gemm
#define NIN 74
#define EIN 12
#define D 64
#define EH 128
#define DD 4096
#define STEPS 6

// ---------------- scratch (static device globals; zero-initialized) ---------
__device__ float    d_h[V_PAD * D];
__device__ float    d_neigh[V_PAD * D];
__device__ __half   d_z[E_PAD * EH];
__device__ __half   d_ew[(size_t)E_PAD * DD];
__device__ uint32_t d_WgF[4 * 8 * 8 * 64];     // fragment-ordered GRU weights (64KB)

// ---------------- asm helpers -------------------------------------------------
__device__ __forceinline__ uint32_t smem_u32(const void* p) {
    uint32_t a;
    asm("{ .reg .u64 t; cvta.to.shared.u64 t, %1; cvt.u32.u64 %0, t; }" : "=r"(a) : "l"(p));
    return a;
}
__device__ __forceinline__ void cp16(uint32_t s, const void* g) {
    asm volatile("cp.async.cg.shared.global [%0], [%1], 16;" :: "r"(s), "l"(g));
}
#define CP_COMMIT() asm volatile("cp.async.commit_group;" ::: "memory")
#define CP_WAIT0()  asm volatile("cp.async.wait_group 0;" ::: "memory")

__device__ __forceinline__ void ldsm_x4(uint32_t addr, uint32_t& r0, uint32_t& r1,
                                        uint32_t& r2, uint32_t& r3) {
    asm volatile("ldmatrix.sync.aligned.m8n8.x4.shared.b16 {%0,%1,%2,%3}, [%4];"
                 : "=r"(r0), "=r"(r1), "=r"(r2), "=r"(r3) : "r"(addr));
}
__device__ __forceinline__ void mma16816(float* c, const uint32_t* a, const uint32_t* b) {
    asm volatile("mma.sync.aligned.m16n8k16.row.col.f32.f16.f16.f32 "
                 "{%0,%1,%2,%3}, {%4,%5,%6,%7}, {%8,%9}, {%0,%1,%2,%3};"
                 : "+f"(c[0]), "+f"(c[1]), "+f"(c[2]), "+f"(c[3])
                 : "r"(a[0]), "r"(a[1]), "r"(a[2]), "r"(a[3]), "r"(b[0]), "r"(b[1]));
}

// packed GRU weight value: Wg[256][128]; rows 0:64 [Wih_r|Whh_r],
// 64:128 [Wih_z|Whh_z], 128:192 [Wih_n|0], 192:256 [0|Whh_n]
__device__ __forceinline__ float wg_val(int r, int k,
                                        const float* __restrict__ Wih,
                                        const float* __restrict__ Whh) {
    if (r < 128)  return (k < 64) ? Wih[r * D + k] : Whh[r * D + (k - 64)];
    if (r < 192)  return (k < 64) ? Wih[r * D + k] : 0.f;
    return (k >= 64) ? Whh[(r - 64) * D + (k - 64)] : 0.f;
}

// ---------------- fused prep: zhid (2500 blk) + proj (1250 blk) + wg (32 blk)
#define ZB 2500
#define PB 1250
#define WB 32
__global__ void prep_all(const float* __restrict__ ef,  const float* __restrict__ W1,
                         const float* __restrict__ b1,  const float* __restrict__ nf,
                         const float* __restrict__ pW,  const float* __restrict__ pb,
                         const float* __restrict__ Wih, const float* __restrict__ Whh) {
    __shared__ char sb[24320];
    const int tid = threadIdx.x;
    const int bx  = blockIdx.x;

    if (bx < ZB) {
        float* W1s = (float*)sb;
        float* b1s = (float*)(sb + 6144);
        float* efs = (float*)(sb + 6656);
        const int e0 = bx * 16;
        for (int idx = tid; idx < EH * EIN; idx += 256) {
            int k = idx / EIN, i = idx % EIN;
            W1s[i * EH + k] = W1[idx];
        }
        for (int idx = tid; idx < 16 * EIN; idx += 256) {
            int e = idx / EIN, i = idx % EIN;
            efs[e * EIN + i] = ef[(size_t)(e0 + e) * EIN + i];
        }
        if (tid < EH) b1s[tid] = b1[tid];
        __syncthreads();
        const int k = tid & 127, g = tid >> 7;
        #pragma unroll
        for (int ee = 0; ee < 8; ee++) {
            int e = g * 8 + ee;
            float acc = b1s[k];
            #pragma unroll
            for (int i = 0; i < EIN; i++)
                acc = fmaf(W1s[i * EH + k], efs[e * EIN + i], acc);
            d_z[(size_t)(e0 + e) * EH + k] = __float2half(fmaxf(acc, 0.f));
        }
    } else if (bx < ZB + PB) {
        float* Ws  = (float*)sb;
        float* nfs = (float*)(sb + 18944);
        float* bs  = (float*)(sb + 23808);
        const int v0 = (bx - ZB) * 16;
        for (int idx = tid; idx < D * NIN; idx += 256) {
            int o = idx / NIN, i = idx % NIN;
            Ws[i * D + o] = pW[idx];
        }
        for (int idx = tid; idx < 16 * NIN; idx += 256) {
            int n = idx / NIN, i = idx % NIN;
            nfs[n * (NIN + 2) + i] = nf[(size_t)(v0 + n) * NIN + i];
        }
        if (tid < D) bs[tid] = pb[tid];
        __syncthreads();
        const int o = tid & 63, g = tid >> 6;
        #pragma unroll
        for (int nn = 0; nn < 4; nn++) {
            int n = g * 4 + nn;
            float acc = bs[o];
            #pragma unroll
            for (int i = 0; i < NIN; i++)
                acc = fmaf(Ws[i * D + o], nfs[n * (NIN + 2) + i], acc);
            d_h[(size_t)(v0 + n) * D + o] = fmaxf(acc, 0.f);
            d_neigh[(size_t)(v0 + n) * D + o] = 0.f;
        }
    } else {
        // fragment-ordered Wg for gate-in-register gru
        int t = (bx - ZB - PB) * 256 + tid;      // 0..8191
        int lane = t & 31, kc = (t >> 5) & 7, j = (t >> 8) & 7, wn = t >> 11;
        int n  = (j >> 1) * 64 + wn * 16 + (j & 1) * 8 + (lane >> 2);
        int k0 = kc * 16 + 2 * (lane & 3);
        __half2 w0 = __floats2half2_rn(wg_val(n, k0,     Wih, Whh),
                                       wg_val(n, k0 + 1, Wih, Whh));
        __half2 w1 = __floats2half2_rn(wg_val(n, k0 + 8, Wih, Whh),
                                       wg_val(n, k0 + 9, Wih, Whh));
        d_WgF[t * 2]     = *(uint32_t*)&w0;
        d_WgF[t * 2 + 1] = *(uint32_t*)&w1;
    }
}

// ---------------- ew GEMM v6: double-buffered A, one sync per tile ------------
// C[E_PAD,4096] = z @ W2^T + b2 (bias in epilogue, fp32)
#define ASTR 136
#define BSTR 152
#define B_BYTES   (128 * BSTR * 2)             // 38912
#define A_BYTES   (128 * ASTR * 2)             // 34816
#define A_OFF     B_BYTES
#define BIAS_OFF  (A_OFF + 2 * A_BYTES)        // 108544
#define EW_SMEM   (BIAS_OFF + 512)             // 109056 -> 2 CTAs/SM (218KB)
#define NSLABS 32
#define MGROUPS 9

__global__ __launch_bounds__(256, 2) void ew_gemm(const float* __restrict__ W2,
                                                  const float* __restrict__ b2) {
    extern __shared__ char smem[];
    __half* Bs     = (__half*)smem;
    float*  bias_s = (float*)(smem + BIAS_OFF);
    const uint32_t sbase = smem_u32(smem);
    const int tid  = threadIdx.x;
    const int lane = tid & 31;
    const int w    = tid >> 5;
    const int wm   = w & 3;        // 4 M groups of 32 rows
    const int wn   = w >> 2;       // 2 N groups of 64 cols
    const int n0   = blockIdx.x * 128;
    const int by   = blockIdx.y;

    // B slab: 128 N-rows x 128 K (f32 -> f16)
    for (int q = tid; q < 4096; q += 256) {
        int n = q >> 5, k4 = (q & 31) * 4;
        float4 v = *(const float4*)&W2[(size_t)(n0 + n) * EH + k4];
        __half t4[4] = { __float2half(v.x), __float2half(v.y),
                         __float2half(v.z), __float2half(v.w) };
        *(uint2*)&Bs[n * BSTR + k4] = *(uint2*)t4;
    }
    if (tid < 128) bias_s[tid] = b2[n0 + tid];
    // prefetch first A tile into buf0
    for (int q = tid; q < 2048; q += 256) {
        int r = q >> 4, c = (q & 15) * 8;
        cp16(sbase + A_OFF + (uint32_t)(r * ASTR + c) * 2,
             &d_z[(size_t)(by * 128 + r) * EH + c]);
    }
    CP_COMMIT();

    // ldsm lane addressing
    const int a_r = lane & 15, a_c = (lane >> 4) * 8;
    const uint32_t aOff = (uint32_t)((wm * 32 + a_r) * ASTR + a_c) * 2;
    const int bm   = lane >> 3;
    const int b_n  = ((bm >> 1) & 1) * 8 + (lane & 7);
    const int b_k  = (bm & 1) * 8;
    const uint32_t bAddr0 = sbase + (uint32_t)((wn * 64 + b_n) * BSTR + b_k) * 2;

    const bool ev = !(lane & 1);
    const int TPT = (NT + MGROUPS - 1) / MGROUPS;
    for (int mt = 0; mt < TPT; mt++) {
        int t = by + MGROUPS * mt;
        if (t >= NT) break;
        CP_WAIT0();                 // G_t is the only pending group
        __syncthreads();            // visibility + protects buf[(mt+1)&1] reuse

        int tn = t + MGROUPS;       // prefetch next into other buffer;
        if (tn < NT) {              // overlaps the whole mma + epilogue
            uint32_t abase = sbase + A_OFF + ((mt + 1) & 1) * A_BYTES;
            for (int q = tid; q < 2048; q += 256) {
                int r = q >> 4, cc = (q & 15) * 8;
                cp16(abase + (uint32_t)(r * ASTR + cc) * 2,
                     &d_z[(size_t)(tn * 128 + r) * EH + cc]);
            }
            CP_COMMIT();
        }

        const uint32_t aAddr0 = sbase + A_OFF + (mt & 1) * A_BYTES + aOff;

        float c[2][8][4];
        #pragma unroll
        for (int i = 0; i < 2; i++)
            #pragma unroll
            for (int j = 0; j < 8; j++)
                #pragma unroll
                for (int q = 0; q < 4; q++) c[i][j][q] = 0.f;

        #pragma unroll
        for (int kc = 0; kc < 8; kc++) {
            uint32_t a[2][4];
            #pragma unroll
            for (int i = 0; i < 2; i++)
                ldsm_x4(aAddr0 + (uint32_t)(i * 16 * ASTR + kc * 16) * 2,
                        a[i][0], a[i][1], a[i][2], a[i][3]);
            #pragma unroll
            for (int jp = 0; jp < 4; jp++) {
                uint32_t b0, b1, b2r, b3;
                ldsm_x4(bAddr0 + (uint32_t)(jp * 16 * BSTR + kc * 16) * 2,
                        b0, b1, b2r, b3);
                uint32_t bj0[2] = { b0, b1 };
                uint32_t bj1[2] = { b2r, b3 };
                #pragma unroll
                for (int i = 0; i < 2; i++) {
                    mma16816(c[i][2 * jp],     a[i], bj0);
                    mma16816(c[i][2 * jp + 1], a[i], bj1);
                }
            }
        }

        // epilogue (registers + shuffles only, no barrier needed)
        const int p_own  = lane & 3;
        const int rbase  = t * 128 + wm * 32 + (lane >> 2);
        const int j_out  = lane & 1;
        const int cchunk = (lane >> 1) & 1;
        #pragma unroll
        for (int jp = 0; jp < 4; jp++) {
            const int j0 = 2 * jp;
            float2 bj0 = *(float2*)&bias_s[(j0)     * 8 + 2 * p_own];
            float2 bj1 = *(float2*)&bias_s[(j0 + 1) * 8 + 2 * p_own];
            #pragma unroll
            for (int i = 0; i < 2; i++) {
                __half2 h0lo = __floats2half2_rn(c[i][j0][0] + bj0.x, c[i][j0][1] + bj0.y);
                __half2 h0hi = __floats2half2_rn(c[i][j0][2] + bj0.x, c[i][j0][3] + bj0.y);
                __half2 h1lo = __floats2half2_rn(c[i][j0+1][0] + bj1.x, c[i][j0+1][1] + bj1.y);
                __half2 h1hi = __floats2half2_rn(c[i][j0+1][2] + bj1.x, c[i][j0+1][3] + bj1.y);
                uint32_t slo = ev ? *(uint32_t*)&h1lo : *(uint32_t*)&h0lo;
                uint32_t shi = ev ? *(uint32_t*)&h1hi : *(uint32_t*)&h0hi;
                uint32_t rlo = __shfl_sync(0xffffffffu, slo, lane ^ 1);
                uint32_t rhi = __shfl_sync(0xffffffffu, shi, lane ^ 1);
                uint32_t klo = ev ? *(uint32_t*)&h0lo : *(uint32_t*)&h1lo;
                uint32_t khi = ev ? *(uint32_t*)&h0hi : *(uint32_t*)&h1hi;
                uint2 outlo = ev ? make_uint2(klo, rlo) : make_uint2(rlo, klo);
                uint2 outhi = ev ? make_uint2(khi, rhi) : make_uint2(rhi, khi);
                int col = n0 + wn * 64 + (j0 + j_out) * 8 + 4 * cchunk;
                size_t rowo = (size_t)(rbase + i * 16) * DD + col;
                *(uint2*)&d_ew[rowo]          = outlo;
                *(uint2*)&d_ew[rowo + 8 * DD] = outhi;
            }
        }
    }
}

// ---------------- per-step kernels -------------------------------------------
// warp per edge, LDG.128 rows (measured at the LTS/HBM cap)
__global__ void scatter_kernel(const int* __restrict__ src, const int* __restrict__ dst) {
    int wg   = (blockIdx.x * blockDim.x + threadIdx.x) >> 5;
    int lane = threadIdx.x & 31;
    if (wg >= E_N) return;
    int se = __ldg(&src[wg]), de = __ldg(&dst[wg]);
    float2 hv = ((const float2*)(d_h + (size_t)se * D))[lane];
    const int4* W4 = (const int4*)(d_ew + (size_t)wg * DD);
    const int rsub = lane >> 3;
    const int cg   = lane & 7;
    float acc[8] = {0.f, 0.f, 0.f, 0.f, 0.f, 0.f, 0.f, 0.f};

    #pragma unroll
    for (int i = 0; i < 16; i++) {
        int r = 4 * i + rsub;
        int4 wv = __ldg(&W4[r * 8 + cg]);
        float hx = __shfl_sync(0xffffffffu, hv.x, 2 * i + (lane >> 4));
        float hy = __shfl_sync(0xffffffffu, hv.y, 2 * i + (lane >> 4));
        float hr = (rsub & 1) ? hy : hx;
        const __half2* wh = (const __half2*)&wv;
        #pragma unroll
        for (int q = 0; q < 4; q++) {
            float2 f = __half22float2(wh[q]);
            acc[2 * q]     = fmaf(hr, f.x, acc[2 * q]);
            acc[2 * q + 1] = fmaf(hr, f.y, acc[2 * q + 1]);
        }
    }
    #pragma unroll
    for (int j = 0; j < 8; j++) {
        acc[j] += __shfl_xor_sync(0xffffffffu, acc[j], 8);
        acc[j] += __shfl_xor_sync(0xffffffffu, acc[j], 16);
    }
    if (lane < 8) {
        float* nb = d_neigh + (size_t)de * D + lane * 8;
        #pragma unroll
        for (int j = 0; j < 8; j++) atomicAdd(nb + j, acc[j]);
    }
}

// GRU v4: gates fully in registers (best measured)
#define GXSTR 136
__global__ __launch_bounds__(256, 4) void gru_mm(const float* __restrict__ conv_b,
                                                 const float* __restrict__ bih,
                                                 const float* __restrict__ bhh) {
    __shared__ __half Xs[32 * GXSTR];
    const int tid  = threadIdx.x;
    const int lane = tid & 31;
    const int w    = tid >> 5;
    const int wm   = w & 1;
    const int wn   = w >> 1;
    const int v0   = blockIdx.x * 32;

    for (int q = tid; q < 512; q += 256) {
        int r = q >> 4, k4 = (q & 15) * 4;
        float4 nv = *(const float4*)&d_neigh[(size_t)(v0 + r) * D + k4];
        float4 cb = *(const float4*)&conv_b[k4];
        float4 hv = *(const float4*)&d_h[(size_t)(v0 + r) * D + k4];
        __half2 x0 = __floats2half2_rn(fmaxf(nv.x + cb.x, 0.f), fmaxf(nv.y + cb.y, 0.f));
        __half2 x1 = __floats2half2_rn(fmaxf(nv.z + cb.z, 0.f), fmaxf(nv.w + cb.w, 0.f));
        __half2 h0 = __floats2half2_rn(hv.x, hv.y);
        __half2 h1 = __floats2half2_rn(hv.z, hv.w);
        *(__half2*)&Xs[r * GXSTR + k4]          = x0;
        *(__half2*)&Xs[r * GXSTR + k4 + 2]      = x1;
        *(__half2*)&Xs[r * GXSTR + 64 + k4]     = h0;
        *(__half2*)&Xs[r * GXSTR + 64 + k4 + 2] = h1;
    }
    __syncthreads();

    const uint32_t xbase = smem_u32(Xs);
    const int a_r = lane & 15, a_c = (lane >> 4) * 8;
    const uint32_t aAddr0 = xbase + (uint32_t)((wm * 16 + a_r) * GXSTR + a_c) * 2;
    const uint2* wf = (const uint2*)(d_WgF) + (size_t)wn * 8 * 8 * 32 + lane;

    float c[8][4];
    #pragma unroll
    for (int j = 0; j < 8; j++)
        #pragma unroll
        for (int q = 0; q < 4; q++) c[j][q] = 0.f;

    #pragma unroll
    for (int kc = 0; kc < 8; kc++) {
        uint32_t a[4];
        ldsm_x4(aAddr0 + kc * 32, a[0], a[1], a[2], a[3]);
        #pragma unroll
        for (int j = 0; j < 8; j++) {
            uint2 bv = __ldg(wf + (j * 8 + kc) * 32);
            uint32_t b[2] = { bv.x, bv.y };
            mma16816(c[j], a, b);
        }
    }

    const int crow = wm * 16 + (lane >> 2);
    const int c0   = wn * 16 + 2 * (lane & 3);
    #pragma unroll
    for (int jh = 0; jh < 2; jh++) {
        const int cb = c0 + jh * 8;
        float sr0 = __ldg(&bih[cb])       + __ldg(&bhh[cb]);
        float sr1 = __ldg(&bih[cb + 1])   + __ldg(&bhh[cb + 1]);
        float sz0 = __ldg(&bih[64 + cb])  + __ldg(&bhh[64 + cb]);
        float sz1 = __ldg(&bih[64 + cb + 1]) + __ldg(&bhh[64 + cb + 1]);
        float bi0 = __ldg(&bih[128 + cb]),     bi1 = __ldg(&bih[128 + cb + 1]);
        float bh0 = __ldg(&bhh[128 + cb]),     bh1 = __ldg(&bhh[128 + cb + 1]);
        #pragma unroll
        for (int pr = 0; pr < 2; pr++) {
            int v = v0 + crow + pr * 8;
            if (v >= V_N) continue;
            size_t gi = (size_t)v * D + cb;
            float2 hp = *(float2*)&d_h[gi];
            int q0 = pr * 2;
            float rg0 = 1.f / (1.f + __expf(-(c[jh][q0]     + sr0)));
            float rg1 = 1.f / (1.f + __expf(-(c[jh][q0 + 1] + sr1)));
            float zg0 = 1.f / (1.f + __expf(-(c[2 + jh][q0]     + sz0)));
            float zg1 = 1.f / (1.f + __expf(-(c[2 + jh][q0 + 1] + sz1)));
            float nx0 = c[4 + jh][q0]     + bi0 + rg0 * (c[6 + jh][q0]     + bh0);
            float nx1 = c[4 + jh][q0 + 1] + bi1 + rg1 * (c[6 + jh][q0 + 1] + bh1);
            float e0 = __expf(2.f * nx0), e1 = __expf(2.f * nx1);
            float ng0 = 1.f - 2.f / (e0 + 1.f);
            float ng1 = 1.f - 2.f / (e1 + 1.f);
            float2 hn;
            hn.x = (1.f - zg0) * ng0 + zg0 * hp.x;
            hn.y = (1.f - zg1) * ng1 + zg1 * hp.y;
            *(float2*)&d_h[gi] = hn;
            *(float2*)&d_neigh[gi] = make_float2(0.f, 0.f);
        }
    }
}

__global__ void pred_kernel(const int* __restrict__ src, const int* __restrict__ dst,
                            const float* __restrict__ pW, const float* __restrict__ pb,
                            float* __restrict__ out) {
    int wg   = (blockIdx.x * blockDim.x + threadIdx.x) >> 5;
    int lane = threadIdx.x & 31;
    if (wg >= E_N) return;
    int se = src[wg], de = dst[wg];
    float2 a  = ((const float2*)(d_h + (size_t)se * D))[lane];
    float2 b  = ((const float2*)(d_h + (size_t)de * D))[lane];
    float2 w1 = ((const float2*)pW)[lane];
    float2 w2 = ((const float2*)pW)[32 + lane];
    float acc = a.x * w1.x + a.y * w1.y + b.x * w2.x + b.y * w2.y;
    #pragma unroll
    for (int off = 16; off > 0; off >>= 1)
        acc += __shfl_down_sync(0xffffffffu, acc, off);
    if (lane == 0) out[wg] = acc + pb[0];
}

// ---------------- launch ------------------------------------------------------
extern "C" void kernel_launch(void* const* d_in, const int* in_sizes, int n_in,
                              void* d_out, int out_size) {
    const float* node_feats = (const float*)d_in[0];
    const float* edge_feats = (const float*)d_in[1];
    const int*   src        = (const int*)d_in[2];
    const int*   dst        = (const int*)d_in[3];
    const float* proj_W     = (const float*)d_in[4];
    const float* proj_b     = (const float*)d_in[5];
    const float* en_W1      = (const float*)d_in[6];
    const float* en_b1      = (const float*)d_in[7];
    const float* en_W2      = (const float*)d_in[8];
    const float* en_b2      = (const float*)d_in[9];
    const float* conv_b     = (const float*)d_in[10];
    const float* gru_Wih    = (const float*)d_in[11];
    const float* gru_Whh    = (const float*)d_in[12];
    const float* gru_bih    = (const float*)d_in[13];
    const float* gru_bhh    = (const float*)d_in[14];
    const float* pred_W     = (const float*)d_in[15];
    const float* pred_b     = (const float*)d_in[16];
    float* out = (float*)d_out;

    static int attr_set = 0;
    if (!attr_set) {
        cudaFuncSetAttribute(ew_gemm, cudaFuncAttributeMaxDynamicSharedMemorySize, EW_SMEM);
        attr_set = 1;
    }

    prep_all<<<ZB + PB + WB, 256>>>(edge_feats, en_W1, en_b1, node_feats,
                                    proj_W, proj_b, gru_Wih, gru_Whh);   // 1
    dim3 gg(NSLABS, MGROUPS);                                            // (32, 9)
    ew_gemm<<<gg, 256, EW_SMEM>>>(en_W2, en_b2);                         // 2

    for (int s = 0; s < STEPS; s++) {
        scatter_kernel<<<E_N / 8, 256>>>(src, dst);                      // 3 on s=0
        gru_mm<<<V_PAD / 32, 256>>>(conv_b, gru_bih, gru_bhh);           // 4 on s=0 (profiled)
    }
    pred_kernel<<<E_N / 8, 256>>>(src, dst, pred_W, pred_b, out);
}

// round 17
// speedup vs baseline: 1.3767x; 1.0037x over previous
#include <cuda_runtime.h>
#include <cuda_fp16.h>
#include <cstdint>

#define V_N 20000
#define V_PAD 20032      // 313 * 64
#define E_N 40000
#define E_PAD 40064      // 313 * 128
#define NT 313           // 128-row M tiles in ew gemm
#define NIN 74
#define EIN 12
#define D 64
#define EH 128
#define DD 4096
#define STEPS 6

// ---------------- scratch (static device globals; zero-initialized) ---------
__device__ float    d_h[V_PAD * D];
__device__ float    d_neigh[V_PAD * D];
__device__ __half   d_z[E_PAD * EH];
__device__ __half   d_ew[(size_t)E_PAD * DD];
__device__ uint32_t d_WgF[4 * 8 * 8 * 64];     // fragment-ordered GRU weights (64KB)

// ---------------- asm helpers -------------------------------------------------
__device__ __forceinline__ uint32_t smem_u32(const void* p) {
    uint32_t a;
    asm("{ .reg .u64 t; cvta.to.shared.u64 t, %1; cvt.u32.u64 %0, t; }" : "=r"(a) : "l"(p));
    return a;
}
__device__ __forceinline__ void cp16(uint32_t s, const void* g) {
    asm volatile("cp.async.cg.shared.global [%0], [%1], 16;" :: "r"(s), "l"(g));
}
#define CP_COMMIT() asm volatile("cp.async.commit_group;" ::: "memory")
#define CP_WAIT0()  asm volatile("cp.async.wait_group 0;" ::: "memory")

__device__ __forceinline__ void ldsm_x4(uint32_t addr, uint32_t& r0, uint32_t& r1,
                                        uint32_t& r2, uint32_t& r3) {
    asm volatile("ldmatrix.sync.aligned.m8n8.x4.shared.b16 {%0,%1,%2,%3}, [%4];"
                 : "=r"(r0), "=r"(r1), "=r"(r2), "=r"(r3) : "r"(addr));
}
__device__ __forceinline__ void mma16816(float* c, const uint32_t* a, const uint32_t* b) {
    asm volatile("mma.sync.aligned.m16n8k16.row.col.f32.f16.f16.f32 "
                 "{%0,%1,%2,%3}, {%4,%5,%6,%7}, {%8,%9}, {%0,%1,%2,%3};"
                 : "+f"(c[0]), "+f"(c[1]), "+f"(c[2]), "+f"(c[3])
                 : "r"(a[0]), "r"(a[1]), "r"(a[2]), "r"(a[3]), "r"(b[0]), "r"(b[1]));
}
__device__ __forceinline__ float tanh_ap(float x) {
    float y;
    asm("tanh.approx.f32 %0, %1;" : "=f"(y) : "f"(x));
    return y;
}
__device__ __forceinline__ float sigmoid_ap(float x) {
    return fmaf(0.5f, tanh_ap(0.5f * x), 0.5f);
}

// packed GRU weight value: Wg[256][128]; rows 0:64 [Wih_r|Whh_r],
// 64:128 [Wih_z|Whh_z], 128:192 [Wih_n|0], 192:256 [0|Whh_n]
__device__ __forceinline__ float wg_val(int r, int k,
                                        const float* __restrict__ Wih,
                                        const float* __restrict__ Whh) {
    if (r < 128)  return (k < 64) ? Wih[r * D + k] : Whh[r * D + (k - 64)];
    if (r < 192)  return (k < 64) ? Wih[r * D + k] : 0.f;
    return (k >= 64) ? Whh[(r - 64) * D + (k - 64)] : 0.f;
}

// ---------------- fused prep: zhid (2500 blk) + proj (1250 blk) + wg (32 blk)
#define ZB 2500
#define PB 1250
#define WB 32
__global__ void prep_all(const float* __restrict__ ef,  const float* __restrict__ W1,
                         const float* __restrict__ b1,  const float* __restrict__ nf,
                         const float* __restrict__ pW,  const float* __restrict__ pb,
                         const float* __restrict__ Wih, const float* __restrict__ Whh) {
    __shared__ char sb[24320];
    const int tid = threadIdx.x;
    const int bx  = blockIdx.x;

    if (bx < ZB) {
        float* W1s = (float*)sb;
        float* b1s = (float*)(sb + 6144);
        float* efs = (float*)(sb + 6656);
        const int e0 = bx * 16;
        for (int idx = tid; idx < EH * EIN; idx += 256) {
            int k = idx / EIN, i = idx % EIN;
            W1s[i * EH + k] = W1[idx];
        }
        for (int idx = tid; idx < 16 * EIN; idx += 256) {
            int e = idx / EIN, i = idx % EIN;
            efs[e * EIN + i] = ef[(size_t)(e0 + e) * EIN + i];
        }
        if (tid < EH) b1s[tid] = b1[tid];
        __syncthreads();
        const int k = tid & 127, g = tid >> 7;
        #pragma unroll
        for (int ee = 0; ee < 8; ee++) {
            int e = g * 8 + ee;
            float acc = b1s[k];
            #pragma unroll
            for (int i = 0; i < EIN; i++)
                acc = fmaf(W1s[i * EH + k], efs[e * EIN + i], acc);
            d_z[(size_t)(e0 + e) * EH + k] = __float2half(fmaxf(acc, 0.f));
        }
    } else if (bx < ZB + PB) {
        float* Ws  = (float*)sb;
        float* nfs = (float*)(sb + 18944);
        float* bs  = (float*)(sb + 23808);
        const int v0 = (bx - ZB) * 16;
        for (int idx = tid; idx < D * NIN; idx += 256) {
            int o = idx / NIN, i = idx % NIN;
            Ws[i * D + o] = pW[idx];
        }
        for (int idx = tid; idx < 16 * NIN; idx += 256) {
            int n = idx / NIN, i = idx % NIN;
            nfs[n * (NIN + 2) + i] = nf[(size_t)(v0 + n) * NIN + i];
        }
        if (tid < D) bs[tid] = pb[tid];
        __syncthreads();
        const int o = tid & 63, g = tid >> 6;
        #pragma unroll
        for (int nn = 0; nn < 4; nn++) {
            int n = g * 4 + nn;
            float acc = bs[o];
            #pragma unroll
            for (int i = 0; i < NIN; i++)
                acc = fmaf(Ws[i * D + o], nfs[n * (NIN + 2) + i], acc);
            d_h[(size_t)(v0 + n) * D + o] = fmaxf(acc, 0.f);
            d_neigh[(size_t)(v0 + n) * D + o] = 0.f;
        }
    } else {
        // fragment-ordered Wg for gate-in-register gru
        int t = (bx - ZB - PB) * 256 + tid;      // 0..8191
        int lane = t & 31, kc = (t >> 5) & 7, j = (t >> 8) & 7, wn = t >> 11;
        int n  = (j >> 1) * 64 + wn * 16 + (j & 1) * 8 + (lane >> 2);
        int k0 = kc * 16 + 2 * (lane & 3);
        __half2 w0 = __floats2half2_rn(wg_val(n, k0,     Wih, Whh),
                                       wg_val(n, k0 + 1, Wih, Whh));
        __half2 w1 = __floats2half2_rn(wg_val(n, k0 + 8, Wih, Whh),
                                       wg_val(n, k0 + 9, Wih, Whh));
        d_WgF[t * 2]     = *(uint32_t*)&w0;
        d_WgF[t * 2 + 1] = *(uint32_t*)&w1;
    }
}

// ---------------- ew GEMM v6: double-buffered A, one sync per tile ------------
// C[E_PAD,4096] = z @ W2^T + b2 (bias in epilogue, fp32)
#define ASTR 136
#define BSTR 152
#define B_BYTES   (128 * BSTR * 2)             // 38912
#define A_BYTES   (128 * ASTR * 2)             // 34816
#define A_OFF     B_BYTES
#define BIAS_OFF  (A_OFF + 2 * A_BYTES)        // 108544
#define EW_SMEM   (BIAS_OFF + 512)             // 109056 -> 2 CTAs/SM (218KB)
#define NSLABS 32
#define MGROUPS 9

__global__ __launch_bounds__(256, 2) void ew_gemm(const float* __restrict__ W2,
                                                  const float* __restrict__ b2) {
    extern __shared__ char smem[];
    __half* Bs     = (__half*)smem;
    float*  bias_s = (float*)(smem + BIAS_OFF);
    const uint32_t sbase = smem_u32(smem);
    const int tid  = threadIdx.x;
    const int lane = tid & 31;
    const int w    = tid >> 5;
    const int wm   = w & 3;        // 4 M groups of 32 rows
    const int wn   = w >> 2;       // 2 N groups of 64 cols
    const int n0   = blockIdx.x * 128;
    const int by   = blockIdx.y;

    // B slab: 128 N-rows x 128 K (f32 -> f16)
    for (int q = tid; q < 4096; q += 256) {
        int n = q >> 5, k4 = (q & 31) * 4;
        float4 v = *(const float4*)&W2[(size_t)(n0 + n) * EH + k4];
        __half t4[4] = { __float2half(v.x), __float2half(v.y),
                         __float2half(v.z), __float2half(v.w) };
        *(uint2*)&Bs[n * BSTR + k4] = *(uint2*)t4;
    }
    if (tid < 128) bias_s[tid] = b2[n0 + tid];
    // prefetch first A tile into buf0
    for (int q = tid; q < 2048; q += 256) {
        int r = q >> 4, c = (q & 15) * 8;
        cp16(sbase + A_OFF + (uint32_t)(r * ASTR + c) * 2,
             &d_z[(size_t)(by * 128 + r) * EH + c]);
    }
    CP_COMMIT();

    const int a_r = lane & 15, a_c = (lane >> 4) * 8;
    const uint32_t aOff = (uint32_t)((wm * 32 + a_r) * ASTR + a_c) * 2;
    const int bm   = lane >> 3;
    const int b_n  = ((bm >> 1) & 1) * 8 + (lane & 7);
    const int b_k  = (bm & 1) * 8;
    const uint32_t bAddr0 = sbase + (uint32_t)((wn * 64 + b_n) * BSTR + b_k) * 2;

    const bool ev = !(lane & 1);
    const int TPT = (NT + MGROUPS - 1) / MGROUPS;
    for (int mt = 0; mt < TPT; mt++) {
        int t = by + MGROUPS * mt;
        if (t >= NT) break;
        CP_WAIT0();
        __syncthreads();

        int tn = t + MGROUPS;
        if (tn < NT) {
            uint32_t abase = sbase + A_OFF + ((mt + 1) & 1) * A_BYTES;
            for (int q = tid; q < 2048; q += 256) {
                int r = q >> 4, cc = (q & 15) * 8;
                cp16(abase + (uint32_t)(r * ASTR + cc) * 2,
                     &d_z[(size_t)(tn * 128 + r) * EH + cc]);
            }
            CP_COMMIT();
        }

        const uint32_t aAddr0 = sbase + A_OFF + (mt & 1) * A_BYTES + aOff;

        float c[2][8][4];
        #pragma unroll
        for (int i = 0; i < 2; i++)
            #pragma unroll
            for (int j = 0; j < 8; j++)
                #pragma unroll
                for (int q = 0; q < 4; q++) c[i][j][q] = 0.f;

        #pragma unroll
        for (int kc = 0; kc < 8; kc++) {
            uint32_t a[2][4];
            #pragma unroll
            for (int i = 0; i < 2; i++)
                ldsm_x4(aAddr0 + (uint32_t)(i * 16 * ASTR + kc * 16) * 2,
                        a[i][0], a[i][1], a[i][2], a[i][3]);
            #pragma unroll
            for (int jp = 0; jp < 4; jp++) {
                uint32_t b0, b1, b2r, b3;
                ldsm_x4(bAddr0 + (uint32_t)(jp * 16 * BSTR + kc * 16) * 2,
                        b0, b1, b2r, b3);
                uint32_t bj0[2] = { b0, b1 };
                uint32_t bj1[2] = { b2r, b3 };
                #pragma unroll
                for (int i = 0; i < 2; i++) {
                    mma16816(c[i][2 * jp],     a[i], bj0);
                    mma16816(c[i][2 * jp + 1], a[i], bj1);
                }
            }
        }

        // epilogue (registers + shuffles only)
        const int p_own  = lane & 3;
        const int rbase  = t * 128 + wm * 32 + (lane >> 2);
        const int j_out  = lane & 1;
        const int cchunk = (lane >> 1) & 1;
        #pragma unroll
        for (int jp = 0; jp < 4; jp++) {
            const int j0 = 2 * jp;
            float2 bj0 = *(float2*)&bias_s[(j0)     * 8 + 2 * p_own];
            float2 bj1 = *(float2*)&bias_s[(j0 + 1) * 8 + 2 * p_own];
            #pragma unroll
            for (int i = 0; i < 2; i++) {
                __half2 h0lo = __floats2half2_rn(c[i][j0][0] + bj0.x, c[i][j0][1] + bj0.y);
                __half2 h0hi = __floats2half2_rn(c[i][j0][2] + bj0.x, c[i][j0][3] + bj0.y);
                __half2 h1lo = __floats2half2_rn(c[i][j0+1][0] + bj1.x, c[i][j0+1][1] + bj1.y);
                __half2 h1hi = __floats2half2_rn(c[i][j0+1][2] + bj1.x, c[i][j0+1][3] + bj1.y);
                uint32_t slo = ev ? *(uint32_t*)&h1lo : *(uint32_t*)&h0lo;
                uint32_t shi = ev ? *(uint32_t*)&h1hi : *(uint32_t*)&h0hi;
                uint32_t rlo = __shfl_sync(0xffffffffu, slo, lane ^ 1);
                uint32_t rhi = __shfl_sync(0xffffffffu, shi, lane ^ 1);
                uint32_t klo = ev ? *(uint32_t*)&h0lo : *(uint32_t*)&h1lo;
                uint32_t khi = ev ? *(uint32_t*)&h0hi : *(uint32_t*)&h1hi;
                uint2 outlo = ev ? make_uint2(klo, rlo) : make_uint2(rlo, klo);
                uint2 outhi = ev ? make_uint2(khi, rhi) : make_uint2(rhi, khi);
                int col = n0 + wn * 64 + (j0 + j_out) * 8 + 4 * cchunk;
                size_t rowo = (size_t)(rbase + i * 16) * DD + col;
                *(uint2*)&d_ew[rowo]          = outlo;
                *(uint2*)&d_ew[rowo + 8 * DD] = outhi;
            }
        }
    }
}

// ---------------- per-step kernels -------------------------------------------
// warp per edge, LDG.128 rows (measured at the LTS/HBM cap)
__global__ void scatter_kernel(const int* __restrict__ src, const int* __restrict__ dst) {
    int wg   = (blockIdx.x * blockDim.x + threadIdx.x) >> 5;
    int lane = threadIdx.x & 31;
    if (wg >= E_N) return;
    int se = __ldg(&src[wg]), de = __ldg(&dst[wg]);
    float2 hv = ((const float2*)(d_h + (size_t)se * D))[lane];
    const int4* W4 = (const int4*)(d_ew + (size_t)wg * DD);
    const int rsub = lane >> 3;
    const int cg   = lane & 7;
    float acc[8] = {0.f, 0.f, 0.f, 0.f, 0.f, 0.f, 0.f, 0.f};

    #pragma unroll
    for (int i = 0; i < 16; i++) {
        int r = 4 * i + rsub;
        int4 wv = __ldg(&W4[r * 8 + cg]);
        float hx = __shfl_sync(0xffffffffu, hv.x, 2 * i + (lane >> 4));
        float hy = __shfl_sync(0xffffffffu, hv.y, 2 * i + (lane >> 4));
        float hr = (rsub & 1) ? hy : hx;
        const __half2* wh = (const __half2*)&wv;
        #pragma unroll
        for (int q = 0; q < 4; q++) {
            float2 f = __half22float2(wh[q]);
            acc[2 * q]     = fmaf(hr, f.x, acc[2 * q]);
            acc[2 * q + 1] = fmaf(hr, f.y, acc[2 * q + 1]);
        }
    }
    #pragma unroll
    for (int j = 0; j < 8; j++) {
        acc[j] += __shfl_xor_sync(0xffffffffu, acc[j], 8);
        acc[j] += __shfl_xor_sync(0xffffffffu, acc[j], 16);
    }
    if (lane < 8) {
        float* nb = d_neigh + (size_t)de * D + lane * 8;
        #pragma unroll
        for (int j = 0; j < 8; j++) atomicAdd(nb + j, acc[j]);
    }
}

// GRU v5: gates in registers + tanh.approx activations (3 MUFU/element)
#define GXSTR 136
__global__ __launch_bounds__(256, 4) void gru_mm(const float* __restrict__ conv_b,
                                                 const float* __restrict__ bih,
                                                 const float* __restrict__ bhh) {
    __shared__ __half Xs[32 * GXSTR];
    const int tid  = threadIdx.x;
    const int lane = tid & 31;
    const int w    = tid >> 5;
    const int wm   = w & 1;
    const int wn   = w >> 1;
    const int v0   = blockIdx.x * 32;

    for (int q = tid; q < 512; q += 256) {
        int r = q >> 4, k4 = (q & 15) * 4;
        float4 nv = *(const float4*)&d_neigh[(size_t)(v0 + r) * D + k4];
        float4 cb = *(const float4*)&conv_b[k4];
        float4 hv = *(const float4*)&d_h[(size_t)(v0 + r) * D + k4];
        __half2 x0 = __floats2half2_rn(fmaxf(nv.x + cb.x, 0.f), fmaxf(nv.y + cb.y, 0.f));
        __half2 x1 = __floats2half2_rn(fmaxf(nv.z + cb.z, 0.f), fmaxf(nv.w + cb.w, 0.f));
        __half2 h0 = __floats2half2_rn(hv.x, hv.y);
        __half2 h1 = __floats2half2_rn(hv.z, hv.w);
        *(__half2*)&Xs[r * GXSTR + k4]          = x0;
        *(__half2*)&Xs[r * GXSTR + k4 + 2]      = x1;
        *(__half2*)&Xs[r * GXSTR + 64 + k4]     = h0;
        *(__half2*)&Xs[r * GXSTR + 64 + k4 + 2] = h1;
    }
    __syncthreads();

    const uint32_t xbase = smem_u32(Xs);
    const int a_r = lane & 15, a_c = (lane >> 4) * 8;
    const uint32_t aAddr0 = xbase + (uint32_t)((wm * 16 + a_r) * GXSTR + a_c) * 2;
    const uint2* wf = (const uint2*)(d_WgF) + (size_t)wn * 8 * 8 * 32 + lane;

    float c[8][4];
    #pragma unroll
    for (int j = 0; j < 8; j++)
        #pragma unroll
        for (int q = 0; q < 4; q++) c[j][q] = 0.f;

    #pragma unroll
    for (int kc = 0; kc < 8; kc++) {
        uint32_t a[4];
        ldsm_x4(aAddr0 + kc * 32, a[0], a[1], a[2], a[3]);
        #pragma unroll
        for (int j = 0; j < 8; j++) {
            uint2 bv = __ldg(wf + (j * 8 + kc) * 32);
            uint32_t b[2] = { bv.x, bv.y };
            mma16816(c[j], a, b);
        }
    }

    const int crow = wm * 16 + (lane >> 2);
    const int c0   = wn * 16 + 2 * (lane & 3);
    #pragma unroll
    for (int jh = 0; jh < 2; jh++) {
        const int cb = c0 + jh * 8;
        float sr0 = __ldg(&bih[cb])       + __ldg(&bhh[cb]);
        float sr1 = __ldg(&bih[cb + 1])   + __ldg(&bhh[cb + 1]);
        float sz0 = __ldg(&bih[64 + cb])  + __ldg(&bhh[64 + cb]);
        float sz1 = __ldg(&bih[64 + cb + 1]) + __ldg(&bhh[64 + cb + 1]);
        float bi0 = __ldg(&bih[128 + cb]),     bi1 = __ldg(&bih[128 + cb + 1]);
        float bh0 = __ldg(&bhh[128 + cb]),     bh1 = __ldg(&bhh[128 + cb + 1]);
        #pragma unroll
        for (int pr = 0; pr < 2; pr++) {
            int v = v0 + crow + pr * 8;
            if (v >= V_N) continue;
            size_t gi = (size_t)v * D + cb;
            float2 hp = *(float2*)&d_h[gi];
            int q0 = pr * 2;
            float rg0 = sigmoid_ap(c[jh][q0]     + sr0);
            float rg1 = sigmoid_ap(c[jh][q0 + 1] + sr1);
            float zg0 = sigmoid_ap(c[2 + jh][q0]     + sz0);
            float zg1 = sigmoid_ap(c[2 + jh][q0 + 1] + sz1);
            float ng0 = tanh_ap(c[4 + jh][q0]     + bi0 + rg0 * (c[6 + jh][q0]     + bh0));
            float ng1 = tanh_ap(c[4 + jh][q0 + 1] + bi1 + rg1 * (c[6 + jh][q0 + 1] + bh1));
            float2 hn;
            hn.x = (1.f - zg0) * ng0 + zg0 * hp.x;
            hn.y = (1.f - zg1) * ng1 + zg1 * hp.y;
            *(float2*)&d_h[gi] = hn;
            *(float2*)&d_neigh[gi] = make_float2(0.f, 0.f);
        }
    }
}

__global__ void pred_kernel(const int* __restrict__ src, const int* __restrict__ dst,
                            const float* __restrict__ pW, const float* __restrict__ pb,
                            float* __restrict__ out) {
    int wg   = (blockIdx.x * blockDim.x + threadIdx.x) >> 5;
    int lane = threadIdx.x & 31;
    if (wg >= E_N) return;
    int se = src[wg], de = dst[wg];
    float2 a  = ((const float2*)(d_h + (size_t)se * D))[lane];
    float2 b  = ((const float2*)(d_h + (size_t)de * D))[lane];
    float2 w1 = ((const float2*)pW)[lane];
    float2 w2 = ((const float2*)pW)[32 + lane];
    float acc = a.x * w1.x + a.y * w1.y + b.x * w2.x + b.y * w2.y;
    #pragma unroll
    for (int off = 16; off > 0; off >>= 1)
        acc += __shfl_down_sync(0xffffffffu, acc, off);
    if (lane == 0) out[wg] = acc + pb[0];
}

// ---------------- launch ------------------------------------------------------
extern "C" void kernel_launch(void* const* d_in, const int* in_sizes, int n_in,
                              void* d_out, int out_size) {
    const float* node_feats = (const float*)d_in[0];
    const float* edge_feats = (const float*)d_in[1];
    const int*   src        = (const int*)d_in[2];
    const int*   dst        = (const int*)d_in[3];
    const float* proj_W     = (const float*)d_in[4];
    const float* proj_b     = (const float*)d_in[5];
    const float* en_W1      = (const float*)d_in[6];
    const float* en_b1      = (const float*)d_in[7];
    const float* en_W2      = (const float*)d_in[8];
    const float* en_b2      = (const float*)d_in[9];
    const float* conv_b     = (const float*)d_in[10];
    const float* gru_Wih    = (const float*)d_in[11];
    const float* gru_Whh    = (const float*)d_in[12];
    const float* gru_bih    = (const float*)d_in[13];
    const float* gru_bhh    = (const float*)d_in[14];
    const float* pred_W     = (const float*)d_in[15];
    const float* pred_b     = (const float*)d_in[16];
    float* out = (float*)d_out;

    static int attr_set = 0;
    if (!attr_set) {
        cudaFuncSetAttribute(ew_gemm, cudaFuncAttributeMaxDynamicSharedMemorySize, EW_SMEM);
        attr_set = 1;
    }

    prep_all<<<ZB + PB + WB, 256>>>(edge_feats, en_W1, en_b1, node_feats,
                                    proj_W, proj_b, gru_Wih, gru_Whh);   // 1
    dim3 gg(NSLABS, MGROUPS);                                            // (32, 9)
    ew_gemm<<<gg, 256, EW_SMEM>>>(en_W2, en_b2);                         // 2

    for (int s = 0; s < STEPS; s++) {
        scatter_kernel<<<E_N / 8, 256>>>(src, dst);                      // 3 on s=0
        gru_mm<<<V_PAD / 32, 256>>>(conv_b, gru_bih, gru_bhh);           // 4 on s=0 (profiled)
    }
    pred_kernel<<<E_N / 8, 256>>>(src, dst, pred_W, pred_b, out);
}